// round 11
// baseline (speedup 1.0000x reference)
#include <cuda_runtime.h>
#include <cuda_fp16.h>
#include <math.h>
#include <stdint.h>

#define CC 256
#define NN 16384
#define BB 4
#define BCN (CC*NN)
#define EGELU 0
#define ESOFT 1
#define EIDENT 2
#define EATTN 3

// hgemm smem geometry (32-bit words)
#define WPITCHW 20                 // W row: 32 halves data + 8 pad = 80B
#define WBUFW (256*WPITCHW)        // 5120 words
#define XPITCHW 72                 // X row: 64 half2 + 8 pad words
#define XBUFW (16*XPITCHW)         // 1152 words
// kv smem
#define KVPITCH 20
#define KVBUF (128*KVPITCH)

__device__ __half g_t  [BB*BCN];   // paired [c2][n]
__device__ __half g_t2 [BB*BCN];   // paired
__device__ __half g_q  [BB*BCN];   // paired
__device__ __half g_k  [BB*BCN];   // plain [c][n]
__device__ __half g_v  [BB*BCN];   // plain
__device__ __half g_g  [BB*BCN];   // plain
__device__ __half g_xp [BB*BCN];   // paired
__device__ __half g_wp16[4*BB*CC*CC];
__device__ __half g_w16 [3*CC*CC];
__device__ __half g_kvT16[BB*CC*CC];
__device__ float  g_kvp[BB*16*CC*CC];
__device__ float  g_ks [BB*CC];
__device__ float  g_ab [2*BB*CC];
__device__ float  g_bp [4*BB*CC];

__device__ __forceinline__ void cpa16s(unsigned s, const void* g){
    asm volatile("cp.async.cg.shared.global [%0], [%1], 16;\n" :: "r"(s), "l"(g));
}
__device__ __forceinline__ void cpacommit(){ asm volatile("cp.async.commit_group;\n"); }
__device__ __forceinline__ void cpawait0(){ asm volatile("cp.async.wait_group 0;\n"); }
__device__ __forceinline__ void mma16(float* d, const unsigned* a, unsigned b0, unsigned b1){
    asm volatile(
      "mma.sync.aligned.m16n8k16.row.col.f32.f16.f16.f32 "
      "{%0,%1,%2,%3},{%4,%5,%6,%7},{%8,%9},{%0,%1,%2,%3};\n"
      : "+f"(d[0]), "+f"(d[1]), "+f"(d[2]), "+f"(d[3])
      : "r"(a[0]), "r"(a[1]), "r"(a[2]), "r"(a[3]), "r"(b0), "r"(b1));
}
__device__ __forceinline__ void ldsm4(unsigned* r, unsigned addr){
    asm volatile("ldmatrix.sync.aligned.m8n8.x4.shared.b16 {%0,%1,%2,%3}, [%4];"
        : "=r"(r[0]), "=r"(r[1]), "=r"(r[2]), "=r"(r[3]) : "r"(addr));
}
__device__ __forceinline__ unsigned packh(float lo, float hi){
    unsigned r;
    asm("cvt.rn.f16x2.f32 %0, %1, %2;" : "=r"(r) : "f"(hi), "f"(lo));
    return r;
}
__device__ __forceinline__ float2 h2f(unsigned u){
    __half2 h = *(__half2*)&u;
    return __half22float2(h);
}
__device__ __forceinline__ float geluf(float x){
    return 0.5f * x * (1.0f + erff(x * 0.70710678118654752440f));
}
__device__ __forceinline__ float softplusf(float x){
    return fmaxf(x, 0.0f) + log1pf(expf(-fabsf(x)));
}
__device__ __forceinline__ float epi_apply(int EPI, float x){
    if (EPI == EGELU) return geluf(x);
    if (EPI == ESOFT) return softplusf(x);
    return x;
}

// ---- merged norm-stats + fp16 pair-pack of x ---------------------------------
__global__ __launch_bounds__(256) void statspack_kernel(
    const float* __restrict__ x, float* __restrict__ ab, __half* __restrict__ xp)
{
    const int b = blockIdx.x >> 7, c2 = blockIdx.x & 127;
    const int tid = threadIdx.x;
    const float* r0 = x + ((long)b*CC + 2*c2)*NN;
    const float* r1 = r0 + NN;
    __half2* xo = (__half2*)xp + (long)(b*128 + c2)*NN;
    float s0=0.f, q0=0.f, s1=0.f, q1=0.f;
    #pragma unroll
    for (int i = 0; i < 16; ++i){
        int idx = (tid + i*256)*4;
        float4 a = *(const float4*)(r0 + idx);
        float4 c = *(const float4*)(r1 + idx);
        s0 += a.x+a.y+a.z+a.w;
        q0 += a.x*a.x + a.y*a.y + a.z*a.z + a.w*a.w;
        s1 += c.x+c.y+c.z+c.w;
        q1 += c.x*c.x + c.y*c.y + c.z*c.z + c.w*c.w;
        *(uint4*)(xo + idx) = make_uint4(packh(a.x,c.x), packh(a.y,c.y),
                                         packh(a.z,c.z), packh(a.w,c.w));
    }
    #pragma unroll
    for (int o = 16; o; o >>= 1){
        s0 += __shfl_xor_sync(0xffffffffu, s0, o);
        q0 += __shfl_xor_sync(0xffffffffu, q0, o);
        s1 += __shfl_xor_sync(0xffffffffu, s1, o);
        q1 += __shfl_xor_sync(0xffffffffu, q1, o);
    }
    __shared__ float sh[32];
    const int w = tid >> 5, lane = tid & 31;
    if (lane == 0){ sh[w] = s0; sh[8+w] = q0; sh[16+w] = s1; sh[24+w] = q1; }
    __syncthreads();
    if (tid < 2){
        float ts = 0.f, tq = 0.f;
        #pragma unroll
        for (int i = 0; i < 8; ++i){ ts += sh[tid*16 + i]; tq += sh[tid*16 + 8 + i]; }
        float mu  = ts * (1.0f/NN);
        float var = tq * (1.0f/NN) - mu*mu;
        float rs  = rsqrtf(var + 1e-5f);
        int c = 2*c2 + tid;
        ab[b*CC + c] = rs;
        ab[BB*CC + b*CC + c] = -mu*rs;
    }
}

struct WT { const float* W[4]; const float* B[4]; };
__global__ __launch_bounds__(256) void wtrans_kernel(
    WT p, const float* __restrict__ ab,
    __half* __restrict__ wp, float* __restrict__ bp)
{
    __shared__ float AL[256], BE[256];
    const int y = blockIdx.x, b = blockIdx.y, rg = blockIdx.z;
    const int tid = threadIdx.x, w = tid >> 5, lane = tid & 31;
    AL[tid] = ab[b*CC + tid];
    BE[tid] = ab[BB*CC + b*CC + tid];
    __syncthreads();
    const float* W = p.W[y];
    __half* wpo = wp + (long)(y*BB + b)*CC*CC;
    const int k0 = lane*8;
    #pragma unroll 1
    for (int pass = 0; pass < 8; ++pass){
        int m = rg*64 + pass*8 + w;
        const float* wr = W + (long)m*CC;
        float4 w0 = *(const float4*)(wr + k0);
        float4 w1 = *(const float4*)(wr + k0 + 4);
        float bacc = w0.x*BE[k0] + w0.y*BE[k0+1] + w0.z*BE[k0+2] + w0.w*BE[k0+3]
                   + w1.x*BE[k0+4] + w1.y*BE[k0+5] + w1.z*BE[k0+6] + w1.w*BE[k0+7];
        unsigned h0 = packh(w0.x*AL[k0],   w0.y*AL[k0+1]);
        unsigned h1 = packh(w0.z*AL[k0+2], w0.w*AL[k0+3]);
        unsigned h2 = packh(w1.x*AL[k0+4], w1.y*AL[k0+5]);
        unsigned h3 = packh(w1.z*AL[k0+6], w1.w*AL[k0+7]);
        *(uint4*)(wpo + (long)m*CC + k0) = make_uint4(h0,h1,h2,h3);
        #pragma unroll
        for (int o = 16; o; o >>= 1) bacc += __shfl_xor_sync(0xffffffffu, bacc, o);
        if (lane == 0) bp[(y*BB + b)*CC + m] = p.B[y][m] + bacc;
    }
}

__global__ __launch_bounds__(256) void cvtw_kernel(
    const float* __restrict__ W0, const float* __restrict__ W1,
    const float* __restrict__ W2, __half* __restrict__ outw)
{
    const float* Ws = (blockIdx.y == 0) ? W0 : (blockIdx.y == 1 ? W1 : W2);
    long i = ((long)blockIdx.x*256 + threadIdx.x)*4;
    float4 v = *(const float4*)(Ws + i);
    unsigned h0 = packh(v.x, v.y), h1 = packh(v.z, v.w);
    *(uint2*)(outw + (long)blockIdx.y*CC*CC + i) = make_uint2(h0, h1);
}

__global__ __launch_bounds__(256) void ksum_kernel(
    const __half* __restrict__ k, float* __restrict__ ks)
{
    const uint4* kp = (const uint4*)(k + (long)blockIdx.x*NN);
    const int tid = threadIdx.x;
    float s = 0.f;
    #pragma unroll
    for (int i = 0; i < 8; ++i){
        uint4 t = kp[tid + i*256];
        float2 f0 = h2f(t.x), f1 = h2f(t.y), f2 = h2f(t.z), f3 = h2f(t.w);
        s += f0.x+f0.y+f1.x+f1.y+f2.x+f2.y+f3.x+f3.y;
    }
    #pragma unroll
    for (int o = 16; o; o >>= 1) s += __shfl_xor_sync(0xffffffffu, s, o);
    __shared__ float sh[8];
    const int w = tid >> 5, lane = tid & 31;
    if (lane == 0) sh[w] = s;
    __syncthreads();
    if (tid == 0){
        float ts = 0.f;
        #pragma unroll
        for (int i = 0; i < 8; ++i) ts += sh[i];
        ks[blockIdx.x] = ts * (1.0f/16.0f);
    }
}

// ---- transposed-formulation GEMM: Y^T[n][m] = X^T[n][k] . W^T[k][m] ----------
// A = X (paired [c2][n] half2, scalar k-pair loads); B = W ([m][k] fp16, ldsm.x4)
struct TP {
    const __half* W[4]; const float* B[4];
    const __half* X[4];
    __half* Y[4];
    float* Yf;
    const __half* Vp; const __half* Gp; const float* ksp;
    int wBatched, bBatched, pairMask;
};

template<int EPI, int ZFUSE, int OUTF32>
__global__ __launch_bounds__(256,2) void hgemm_kernel(TP p)
{
    extern __shared__ float sm[];
    float* BIs = sm + 2*WBUFW + 2*XBUFW;   // 256
    float* KSs = BIs + 256;                // 256
    float* ZSs = KSs + 256;                // 64
    const unsigned sbase = (unsigned)__cvta_generic_to_shared(sm);

    const int tid = threadIdx.x, w = tid >> 5, lane = tid & 31;
    const int g = lane >> 2, lr = lane & 3;
    const int mtile = w & 3, chalf = w >> 2;
    const int y = blockIdx.y;
    const int b = blockIdx.z;
    const long n0 = (long)blockIdx.x * 64;
    const __half* W1 = p.W[y] + (p.wBatched ? (long)b*CC*CC : 0);
    const __half2* X2 = (const __half2*)p.X[y] + (long)b*(BCN/2);

    if (ZFUSE) KSs[tid] = p.ksp[b*CC + tid];
    if (EPI != EATTN) BIs[tid] = p.B[y][(p.bBatched ? b*CC : 0) + tid];

    auto loadChunk = [&](int kc, int buf){
        const unsigned wbase = sbase + (unsigned)buf*(WBUFW*4);
        const unsigned xbase = sbase + (unsigned)(2*WBUFW*4) + (unsigned)buf*(XBUFW*4);
        #pragma unroll
        for (int i = 0; i < 4; ++i){
            int idx = tid + i*256;
            int r = idx >> 2, c = idx & 3;
            cpa16s(wbase + (unsigned)(r*80 + c*16), W1 + (long)r*CC + kc*32 + c*8);
        }
        {
            int r = tid >> 4, c = tid & 15;
            cpa16s(xbase + (unsigned)(r*288 + c*16), X2 + (long)(kc*16 + r)*NN + n0 + c*4);
        }
        cpacommit();
    };

    loadChunk(0, 0);

    float acc[16][4];
    #pragma unroll
    for (int nt = 0; nt < 16; ++nt)
        #pragma unroll
        for (int i = 0; i < 4; ++i) acc[nt][i] = 0.f;
    float zreg = 0.f;

    // ldsm base for W fragments (pairs of n8 tiles)
    const unsigned wl_row = (unsigned)(chalf*128 + ((lane >> 4) & 1)*8 + (lane & 7));
    const unsigned wl_koff = (unsigned)((lane >> 3) & 1)*16u;
    const int nwb = mtile*16;

    #pragma unroll 1
    for (int kc = 0; kc < 8; ++kc){
        cpawait0();
        __syncthreads();
        if (kc < 7) loadChunk(kc+1, (kc+1)&1);
        const unsigned wbuf = sbase + (unsigned)(kc&1)*(WBUFW*4);
        const unsigned* Xu = (const unsigned*)(sm + 2*WBUFW + (kc&1)*XBUFW);
        if (ZFUSE && tid < 64){
            #pragma unroll
            for (int kk = 0; kk < 16; ++kk){
                float2 f = h2f(Xu[kk*XPITCHW + tid]);
                zreg = fmaf(f.x, KSs[kc*32 + 2*kk],     zreg);
                zreg = fmaf(f.y, KSs[kc*32 + 2*kk + 1], zreg);
            }
        }
        const unsigned wls = wbuf + wl_row*80u + wl_koff;
        #pragma unroll
        for (int s = 0; s < 2; ++s){
            unsigned a[4];
            a[0] = Xu[(s*8     + lr)*XPITCHW + nwb + g    ];
            a[1] = Xu[(s*8     + lr)*XPITCHW + nwb + g + 8];
            a[2] = Xu[(s*8 + 4 + lr)*XPITCHW + nwb + g    ];
            a[3] = Xu[(s*8 + 4 + lr)*XPITCHW + nwb + g + 8];
            const unsigned ks32 = (unsigned)s*32u;
            #pragma unroll
            for (int ntp = 0; ntp < 8; ++ntp){
                unsigned bb[4];
                ldsm4(bb, wls + (unsigned)(ntp*16*80) + ks32);
                mma16(acc[2*ntp  ], a, bb[0], bb[1]);
                mma16(acc[2*ntp+1], a, bb[2], bb[3]);
            }
        }
        __syncthreads();
    }

    if (ZFUSE){
        if (tid < 64) ZSs[tid] = 1.0f / (zreg + (float)NN);
        __syncthreads();
    }

    const int pair = (p.pairMask >> y) & 1;
    const long gn0 = n0 + nwb + g;
    const long gn1 = gn0 + 8;
    float zz0 = 0.f, zz1 = 0.f;
    if (EPI == EATTN){ zz0 = ZSs[nwb + g]; zz1 = ZSs[nwb + g + 8]; }

    #pragma unroll
    for (int nt = 0; nt < 16; ++nt){
        const int c = chalf*128 + nt*8 + 2*lr;
        float d0 = acc[nt][0], d1 = acc[nt][1], d2 = acc[nt][2], d3 = acc[nt][3];
        if (EPI == EATTN){
            const __half* Vb = p.Vp + (long)b*BCN;
            const __half* Gb = p.Gp + (long)b*BCN;
            float v00 = __half2float(Vb[(long)c*NN + gn0]);
            float v01 = __half2float(Vb[(long)(c+1)*NN + gn0]);
            float v10 = __half2float(Vb[(long)c*NN + gn1]);
            float v11 = __half2float(Vb[(long)(c+1)*NN + gn1]);
            float g00 = __half2float(Gb[(long)c*NN + gn0]);
            float g01 = __half2float(Gb[(long)(c+1)*NN + gn0]);
            float g10 = __half2float(Gb[(long)c*NN + gn1]);
            float g11 = __half2float(Gb[(long)(c+1)*NN + gn1]);
            d0 = (d0 + v00) * zz0 * g00;
            d1 = (d1 + v01) * zz0 * g01;
            d2 = (d2 + v10) * zz1 * g10;
            d3 = (d3 + v11) * zz1 * g11;
        } else {
            const float bi0 = BIs[c], bi1 = BIs[c+1];
            d0 = epi_apply(EPI, d0 + bi0);
            d1 = epi_apply(EPI, d1 + bi1);
            d2 = epi_apply(EPI, d2 + bi0);
            d3 = epi_apply(EPI, d3 + bi1);
        }
        if (OUTF32){
            float* Yf = p.Yf + (long)b*BCN;
            Yf[(long)c*NN + gn0]     = d0;
            Yf[(long)(c+1)*NN + gn0] = d1;
            Yf[(long)c*NN + gn1]     = d2;
            Yf[(long)(c+1)*NN + gn1] = d3;
        } else if (pair){
            __half2* Y2 = (__half2*)p.Y[y] + (long)b*(BCN/2);
            *(unsigned*)(Y2 + (long)(c>>1)*NN + gn0) = packh(d0, d1);
            *(unsigned*)(Y2 + (long)(c>>1)*NN + gn1) = packh(d2, d3);
        } else {
            __half* Yh = p.Y[y] + (long)b*BCN;
            Yh[(long)c*NN + gn0]     = __float2half_rn(d0);
            Yh[(long)(c+1)*NN + gn0] = __float2half_rn(d1);
            Yh[(long)c*NN + gn1]     = __float2half_rn(d2);
            Yh[(long)(c+1)*NN + gn1] = __float2half_rn(d3);
        }
    }
}

__global__ __launch_bounds__(256,2) void kv_kernel(
    const __half* __restrict__ K, const __half* __restrict__ V, float* __restrict__ P)
{
    extern __shared__ float sm[];
    const unsigned sbase = (unsigned)__cvta_generic_to_shared(sm);
    const int tid = threadIdx.x, w = tid >> 5, lane = tid & 31;
    const int g = lane >> 2, lr = lane & 3;
    const int wm = w & 3, wn = w >> 2;
    const int c0 = (blockIdx.x & 1) * 128;
    const int d0 = (blockIdx.x >> 1) * 128;
    const int chunk = blockIdx.y;
    const int b = blockIdx.z;
    const __half* Kb = K + (long)b*BCN;
    const __half* Vb = V + (long)b*BCN;
    const long nbase = (long)chunk * 1024;

    const unsigned kaoff0 = (unsigned)((wm*32 + (lane & 15))*KVPITCH)*4u + (unsigned)(lane >> 4)*16u;
    const unsigned kaoff1 = kaoff0 + (unsigned)(16*KVPITCH)*4u;
    const unsigned kboff  = (unsigned)((wn*64 + ((lane >> 4) & 1)*8 + (lane & 7))*KVPITCH)*4u
                          + (unsigned)((lane >> 3) & 1)*16u;

    auto loadChunk = [&](long nb, int buf){
        const unsigned abase = sbase + (unsigned)buf*(KVBUF*4);
        const unsigned bbase = sbase + (unsigned)(2*KVBUF*4) + (unsigned)buf*(KVBUF*4);
        #pragma unroll
        for (int i = 0; i < 2; ++i){
            int idx = tid + i*256;
            int r = idx >> 2, c8 = idx & 3;
            cpa16s(abase + (unsigned)(r*80 + c8*16), Kb + (long)(c0+r)*NN + nb + c8*8);
            cpa16s(bbase + (unsigned)(r*80 + c8*16), Vb + (long)(d0+r)*NN + nb + c8*8);
        }
        cpacommit();
    };

    loadChunk(nbase, 0);

    float acc[2][8][4];
    #pragma unroll
    for (int mt = 0; mt < 2; ++mt)
        #pragma unroll
        for (int nt = 0; nt < 8; ++nt)
            #pragma unroll
            for (int i = 0; i < 4; ++i) acc[mt][nt][i] = 0.f;

    #pragma unroll 1
    for (int it = 0; it < 32; ++it){
        cpawait0();
        __syncthreads();
        if (it < 31) loadChunk(nbase + (long)(it+1)*32, (it+1)&1);
        const unsigned abuf = sbase + (unsigned)(it&1)*(KVBUF*4);
        const unsigned bbuf = sbase + (unsigned)(2*KVBUF*4) + (unsigned)(it&1)*(KVBUF*4);
        #pragma unroll
        for (int s = 0; s < 2; ++s){
            const unsigned sb = (unsigned)s*32u;
            unsigned a0[4], a1[4];
            ldsm4(a0, abuf + kaoff0 + sb);
            ldsm4(a1, abuf + kaoff1 + sb);
            #pragma unroll
            for (int ntp = 0; ntp < 4; ++ntp){
                unsigned bb[4];
                ldsm4(bb, bbuf + kboff + (unsigned)(ntp*16*KVPITCH)*4u + sb);
                mma16(acc[0][2*ntp  ], a0, bb[0], bb[1]);
                mma16(acc[1][2*ntp  ], a1, bb[0], bb[1]);
                mma16(acc[0][2*ntp+1], a0, bb[2], bb[3]);
                mma16(acc[1][2*ntp+1], a1, bb[2], bb[3]);
            }
        }
        __syncthreads();
    }

    float* Pb = P + (long)(b*16 + chunk)*CC*CC;
    #pragma unroll
    for (int mt = 0; mt < 2; ++mt){
        #pragma unroll
        for (int half = 0; half < 2; ++half){
            const int r = c0 + wm*32 + mt*16 + g + half*8;
            #pragma unroll
            for (int nt = 0; nt < 8; ++nt){
                const int d = d0 + wn*64 + nt*8 + lr*2;
                float2 o;
                o.x = acc[mt][nt][half*2+0];
                o.y = acc[mt][nt][half*2+1];
                *(float2*)(Pb + (long)r*CC + d) = o;
            }
        }
    }
}

__global__ __launch_bounds__(256) void kvred_kernel(
    const float* __restrict__ P, __half* __restrict__ kvT)
{
    const int o = blockIdx.x * 256 + threadIdx.x;
    const int b = o >> 16;
    const int c = (o >> 8) & 255;
    const int d = o & 255;
    float s = 0.f;
    #pragma unroll
    for (int ch = 0; ch < 16; ++ch)
        s += P[((long)(b*16 + ch)*256 + c)*256 + d];
    kvT[((long)b*256 + d)*256 + c] = __float2half_rn(s * (1.0f/16.0f));
}

static const size_t HG_SMEM = (size_t)(2*WBUFW + 2*XBUFW + 576) * sizeof(float); // 52480
static const size_t KV_SMEM = (size_t)(4*KVBUF) * sizeof(float);

extern "C" void kernel_launch(void* const* d_in, const int* in_sizes, int n_in,
                              void* d_out, int out_size)
{
    (void)in_sizes; (void)n_in; (void)out_size;
    const float* x   = (const float*)d_in[0];
    const float* Wq1 = (const float*)d_in[1];  const float* bq1 = (const float*)d_in[2];
    const float* Wq2 = (const float*)d_in[3];  const float* bq2 = (const float*)d_in[4];
    const float* Wk1 = (const float*)d_in[5];  const float* bk1 = (const float*)d_in[6];
    const float* Wk2 = (const float*)d_in[7];  const float* bk2 = (const float*)d_in[8];
    const float* Wv  = (const float*)d_in[9];  const float* bv  = (const float*)d_in[10];
    const float* Wg  = (const float*)d_in[11]; const float* bg  = (const float*)d_in[12];
    const float* Wo  = (const float*)d_in[13]; const float* bo  = (const float*)d_in[14];
    float* out = (float*)d_out;

    __half *t, *t2, *q, *k, *v, *g, *xp, *wp16, *w16, *kvT16;
    float *kvp, *ks, *ab, *bp;
    cudaGetSymbolAddress((void**)&t,     g_t);
    cudaGetSymbolAddress((void**)&t2,    g_t2);
    cudaGetSymbolAddress((void**)&q,     g_q);
    cudaGetSymbolAddress((void**)&k,     g_k);
    cudaGetSymbolAddress((void**)&v,     g_v);
    cudaGetSymbolAddress((void**)&g,     g_g);
    cudaGetSymbolAddress((void**)&xp,    g_xp);
    cudaGetSymbolAddress((void**)&wp16,  g_wp16);
    cudaGetSymbolAddress((void**)&w16,   g_w16);
    cudaGetSymbolAddress((void**)&kvT16, g_kvT16);
    cudaGetSymbolAddress((void**)&kvp,   g_kvp);
    cudaGetSymbolAddress((void**)&ks,    g_ks);
    cudaGetSymbolAddress((void**)&ab,    g_ab);
    cudaGetSymbolAddress((void**)&bp,    g_bp);

    cudaFuncSetAttribute((const void*)hgemm_kernel<EGELU,0,0>,
                         cudaFuncAttributeMaxDynamicSharedMemorySize, (int)HG_SMEM);
    cudaFuncSetAttribute((const void*)hgemm_kernel<ESOFT,0,0>,
                         cudaFuncAttributeMaxDynamicSharedMemorySize, (int)HG_SMEM);
    cudaFuncSetAttribute((const void*)hgemm_kernel<EATTN,1,0>,
                         cudaFuncAttributeMaxDynamicSharedMemorySize, (int)HG_SMEM);
    cudaFuncSetAttribute((const void*)hgemm_kernel<EIDENT,0,1>,
                         cudaFuncAttributeMaxDynamicSharedMemorySize, (int)HG_SMEM);
    cudaFuncSetAttribute((const void*)kv_kernel,
                         cudaFuncAttributeMaxDynamicSharedMemorySize, (int)KV_SMEM);

    statspack_kernel<<<BB*128, 256>>>(x, ab, xp);
    {
        WT wt;
        wt.W[0]=Wq1; wt.B[0]=bq1;
        wt.W[1]=Wk1; wt.B[1]=bk1;
        wt.W[2]=Wv;  wt.B[2]=bv;
        wt.W[3]=Wg;  wt.B[3]=bg;
        dim3 grid(4, BB, 4);
        wtrans_kernel<<<grid, 256>>>(wt, ab, wp16, bp);
    }
    {
        dim3 grid(64, 3);
        cvtw_kernel<<<grid, 256>>>(Wq2, Wk2, Wo, w16);
    }

    {   // stage-1 (gelu): q1->t(pair), k1->t2(pair), v(plain), g(plain)
        TP p = {};
        p.W[0]=wp16 + 0L*BB*CC*CC; p.B[0]=bp + 0*BB*CC; p.X[0]=xp; p.Y[0]=t;
        p.W[1]=wp16 + 1L*BB*CC*CC; p.B[1]=bp + 1*BB*CC; p.X[1]=xp; p.Y[1]=t2;
        p.W[2]=wp16 + 2L*BB*CC*CC; p.B[2]=bp + 2*BB*CC; p.X[2]=xp; p.Y[2]=v;
        p.W[3]=wp16 + 3L*BB*CC*CC; p.B[3]=bp + 3*BB*CC; p.X[3]=xp; p.Y[3]=g;
        p.wBatched = 1; p.bBatched = 1; p.pairMask = 0b0011;
        dim3 grid(NN/64, 4, BB);
        hgemm_kernel<EGELU,0,0><<<grid, 256, HG_SMEM>>>(p);
    }
    {   // stage-2 (softplus): q2: t->q(pair), k2: t2->k(plain)
        TP p = {};
        p.W[0]=w16 + 0L*CC*CC; p.B[0]=bq2; p.X[0]=t;  p.Y[0]=q;
        p.W[1]=w16 + 1L*CC*CC; p.B[1]=bk2; p.X[1]=t2; p.Y[1]=k;
        p.wBatched = 0; p.bBatched = 0; p.pairMask = 0b01;
        dim3 grid(NN/64, 2, BB);
        hgemm_kernel<ESOFT,0,0><<<grid, 256, HG_SMEM>>>(p);
    }
    ksum_kernel<<<BB*CC, 256>>>(k, ks);
    {
        dim3 grid(4, 16, BB);
        kv_kernel<<<grid, 256, KV_SMEM>>>(k, v, kvp);
    }
    kvred_kernel<<<BB*CC, 256>>>(kvp, kvT16);
    {   // attn: t = (kvT.q + v) * z * g   (paired out)
        TP p = {};
        p.W[0]=kvT16; p.B[0]=nullptr; p.X[0]=q; p.Y[0]=t;
        p.Vp = v; p.Gp = g; p.ksp = ks;
        p.wBatched = 1; p.bBatched = 0; p.pairMask = 0b1;
        dim3 grid(NN/64, 1, BB);
        hgemm_kernel<EATTN,1,0><<<grid, 256, HG_SMEM>>>(p);
    }
    {   // final: out = Wo.t + bo (f32 out)
        TP p = {};
        p.W[0]=w16 + 2L*CC*CC; p.B[0]=bo; p.X[0]=t; p.Yf = out;
        p.wBatched = 0; p.bBatched = 0; p.pairMask = 0;
        dim3 grid(NN/64, 1, BB);
        hgemm_kernel<EIDENT,0,1><<<grid, 256, HG_SMEM>>>(p);
    }
}

// round 12
// speedup vs baseline: 1.0207x; 1.0207x over previous
#include <cuda_runtime.h>
#include <cuda_fp16.h>
#include <math.h>
#include <stdint.h>

#define CC 256
#define NN 16384
#define BB 4
#define BCN (CC*NN)
#define EGELU 0
#define ESOFT 1
#define EIDENT 2
#define EATTN 3

// hgemm smem geometry (32-bit words)
#define WPITCH 20                  // W row: 32 halves + pad = 80 B
#define WBUF (256*WPITCH)          // 5120 words per buffer
#define XPITCH 36                  // X row: 64 halves + pad = 144 B
#define XBUF (32*XPITCH)           // 1152 words per buffer (32 k rows)
// kv smem
#define KVPITCH 20
#define KVBUF (128*KVPITCH)

__device__ __half g_t  [BB*BCN];   // plain [c][n]
__device__ __half g_t2 [BB*BCN];
__device__ __half g_q  [BB*BCN];
__device__ __half g_k  [BB*BCN];
__device__ __half g_v  [BB*BCN];
__device__ __half g_g  [BB*BCN];
__device__ __half g_xh [BB*BCN];   // plain fp16 x
__device__ __half g_wp16[4*BB*CC*CC];
__device__ __half g_w16 [3*CC*CC];
__device__ __half g_kvT16[BB*CC*CC];
__device__ float  g_kvp[BB*16*CC*CC];
__device__ float  g_ks [BB*CC];
__device__ float  g_ab [2*BB*CC];
__device__ float  g_bp [4*BB*CC];

__device__ __forceinline__ void cpa16s(unsigned s, const void* g){
    asm volatile("cp.async.cg.shared.global [%0], [%1], 16;\n" :: "r"(s), "l"(g));
}
__device__ __forceinline__ void cpacommit(){ asm volatile("cp.async.commit_group;\n"); }
__device__ __forceinline__ void cpawait0(){ asm volatile("cp.async.wait_group 0;\n"); }
__device__ __forceinline__ void mma16(float* d, const unsigned* a, unsigned b0, unsigned b1){
    asm volatile(
      "mma.sync.aligned.m16n8k16.row.col.f32.f16.f16.f32 "
      "{%0,%1,%2,%3},{%4,%5,%6,%7},{%8,%9},{%0,%1,%2,%3};\n"
      : "+f"(d[0]), "+f"(d[1]), "+f"(d[2]), "+f"(d[3])
      : "r"(a[0]), "r"(a[1]), "r"(a[2]), "r"(a[3]), "r"(b0), "r"(b1));
}
__device__ __forceinline__ void ldsm4(unsigned* r, unsigned addr){
    asm volatile("ldmatrix.sync.aligned.m8n8.x4.shared.b16 {%0,%1,%2,%3}, [%4];"
        : "=r"(r[0]), "=r"(r[1]), "=r"(r[2]), "=r"(r[3]) : "r"(addr));
}
__device__ __forceinline__ void ldsm4t(unsigned* r, unsigned addr){
    asm volatile("ldmatrix.sync.aligned.m8n8.x4.trans.shared.b16 {%0,%1,%2,%3}, [%4];"
        : "=r"(r[0]), "=r"(r[1]), "=r"(r[2]), "=r"(r[3]) : "r"(addr));
}
__device__ __forceinline__ unsigned packh(float lo, float hi){
    unsigned r;
    asm("cvt.rn.f16x2.f32 %0, %1, %2;" : "=r"(r) : "f"(hi), "f"(lo));
    return r;
}
__device__ __forceinline__ float2 h2f(unsigned u){
    __half2 h = *(__half2*)&u;
    return __half22float2(h);
}
__device__ __forceinline__ float geluf(float x){
    return 0.5f * x * (1.0f + erff(x * 0.70710678118654752440f));
}
__device__ __forceinline__ float softplusf(float x){
    return fmaxf(x, 0.0f) + log1pf(expf(-fabsf(x)));
}
__device__ __forceinline__ float epi_apply(int EPI, float x){
    if (EPI == EGELU) return geluf(x);
    if (EPI == ESOFT) return softplusf(x);
    return x;
}

// ---- merged norm-stats + plain fp16 convert of x -----------------------------
__global__ __launch_bounds__(256) void statspack_kernel(
    const float* __restrict__ x, float* __restrict__ ab, __half* __restrict__ xh)
{
    const long base = (long)blockIdx.x * NN;
    const float4* xp = (const float4*)(x + base);
    uint2* xo = (uint2*)(xh + base);
    const int tid = threadIdx.x;
    float s = 0.f, q = 0.f;
    #pragma unroll
    for (int i = 0; i < 16; ++i){
        float4 t = xp[tid + i*256];
        s += t.x + t.y + t.z + t.w;
        q += t.x*t.x + t.y*t.y + t.z*t.z + t.w*t.w;
        xo[tid + i*256] = make_uint2(packh(t.x, t.y), packh(t.z, t.w));
    }
    #pragma unroll
    for (int o = 16; o; o >>= 1){
        s += __shfl_xor_sync(0xffffffffu, s, o);
        q += __shfl_xor_sync(0xffffffffu, q, o);
    }
    __shared__ float sh[16];
    const int w = tid >> 5, lane = tid & 31;
    if (lane == 0){ sh[w] = s; sh[8+w] = q; }
    __syncthreads();
    if (tid == 0){
        float ts = 0.f, tq = 0.f;
        #pragma unroll
        for (int i = 0; i < 8; ++i){ ts += sh[i]; tq += sh[8+i]; }
        float mu  = ts * (1.0f/NN);
        float var = tq * (1.0f/NN) - mu*mu;
        float rs  = rsqrtf(var + 1e-5f);
        ab[blockIdx.x] = rs;
        ab[BB*CC + blockIdx.x] = -mu*rs;
    }
}

struct WT { const float* W[4]; const float* B[4]; };
__global__ __launch_bounds__(256) void wtrans_kernel(
    WT p, const float* __restrict__ ab,
    __half* __restrict__ wp, float* __restrict__ bp)
{
    __shared__ float AL[256], BE[256];
    const int y = blockIdx.x, b = blockIdx.y, rg = blockIdx.z;
    const int tid = threadIdx.x, w = tid >> 5, lane = tid & 31;
    AL[tid] = ab[b*CC + tid];
    BE[tid] = ab[BB*CC + b*CC + tid];
    __syncthreads();
    const float* W = p.W[y];
    __half* wpo = wp + (long)(y*BB + b)*CC*CC;
    const int k0 = lane*8;
    #pragma unroll 1
    for (int pass = 0; pass < 8; ++pass){
        int m = rg*64 + pass*8 + w;
        const float* wr = W + (long)m*CC;
        float4 w0 = *(const float4*)(wr + k0);
        float4 w1 = *(const float4*)(wr + k0 + 4);
        float bacc = w0.x*BE[k0] + w0.y*BE[k0+1] + w0.z*BE[k0+2] + w0.w*BE[k0+3]
                   + w1.x*BE[k0+4] + w1.y*BE[k0+5] + w1.z*BE[k0+6] + w1.w*BE[k0+7];
        unsigned h0 = packh(w0.x*AL[k0],   w0.y*AL[k0+1]);
        unsigned h1 = packh(w0.z*AL[k0+2], w0.w*AL[k0+3]);
        unsigned h2 = packh(w1.x*AL[k0+4], w1.y*AL[k0+5]);
        unsigned h3 = packh(w1.z*AL[k0+6], w1.w*AL[k0+7]);
        *(uint4*)(wpo + (long)m*CC + k0) = make_uint4(h0,h1,h2,h3);
        #pragma unroll
        for (int o = 16; o; o >>= 1) bacc += __shfl_xor_sync(0xffffffffu, bacc, o);
        if (lane == 0) bp[(y*BB + b)*CC + m] = p.B[y][m] + bacc;
    }
}

__global__ __launch_bounds__(256) void cvtw_kernel(
    const float* __restrict__ W0, const float* __restrict__ W1,
    const float* __restrict__ W2, __half* __restrict__ outw)
{
    const float* Ws = (blockIdx.y == 0) ? W0 : (blockIdx.y == 1 ? W1 : W2);
    long i = ((long)blockIdx.x*256 + threadIdx.x)*4;
    float4 v = *(const float4*)(Ws + i);
    unsigned h0 = packh(v.x, v.y), h1 = packh(v.z, v.w);
    *(uint2*)(outw + (long)blockIdx.y*CC*CC + i) = make_uint2(h0, h1);
}

__global__ __launch_bounds__(256) void ksum_kernel(
    const __half* __restrict__ k, float* __restrict__ ks)
{
    const uint4* kp = (const uint4*)(k + (long)blockIdx.x*NN);
    const int tid = threadIdx.x;
    float s = 0.f;
    #pragma unroll
    for (int i = 0; i < 8; ++i){
        uint4 t = kp[tid + i*256];
        float2 f0 = h2f(t.x), f1 = h2f(t.y), f2 = h2f(t.z), f3 = h2f(t.w);
        s += f0.x+f0.y+f1.x+f1.y+f2.x+f2.y+f3.x+f3.y;
    }
    #pragma unroll
    for (int o = 16; o; o >>= 1) s += __shfl_xor_sync(0xffffffffu, s, o);
    __shared__ float sh[8];
    const int w = tid >> 5, lane = tid & 31;
    if (lane == 0) sh[w] = s;
    __syncthreads();
    if (tid == 0){
        float ts = 0.f;
        #pragma unroll
        for (int i = 0; i < 8; ++i) ts += sh[i];
        ks[blockIdx.x] = ts * (1.0f/16.0f);
    }
}

// ---- GEMM: Y[m][n] = epi( sum_k W[m][k] * X[k][n] + bias[m] ) ----------------
// A = W [m][k] (ldsm non-trans), B = X plain [k][n] (ldsm.x4.trans)
struct TP {
    const __half* W[4]; const float* B[4];
    const __half* X[4];
    __half* Y[4];
    float* Yf;
    const __half* Vp; const __half* Gp; const float* ksp;
    int wBatched, bBatched;
};

template<int EPI, int ZFUSE, int OUTF32>
__global__ __launch_bounds__(256,2) void hgemm_kernel(TP p)
{
    extern __shared__ float sm[];
    float* KSs = sm + 2*WBUF + 2*XBUF;   // 256
    float* ZSs = KSs + 256;              // 64
    const unsigned sbase = (unsigned)__cvta_generic_to_shared(sm);

    const int tid = threadIdx.x, w = tid >> 5, lane = tid & 31;
    const int g = lane >> 2, lr = lane & 3;
    const int y = blockIdx.y;
    const int b = blockIdx.z;
    const long n0 = (long)blockIdx.x * 64;
    const __half* W1 = p.W[y] + (p.wBatched ? (long)b*CC*CC : 0);
    const __half* Xh = p.X[y] + (long)b*BCN;

    if (ZFUSE) KSs[tid] = p.ksp[b*CC + tid];

    // A (W) ldsm base: rows w*32 + (lane&15), col-byte (lane>>4)*16
    const unsigned aoff0 = (unsigned)((w*32 + (lane & 15))*WPITCH)*4u + (unsigned)(lane >> 4)*16u;
    const unsigned aoff1 = aoff0 + (unsigned)(16*WPITCH)*4u;
    // B (X) ldsm.trans base: rows (ti&1)*8 + (lane&7), col-byte (ti>>1)*16, ti=lane>>3
    const unsigned boff = (unsigned)((((lane >> 3) & 1)*8 + (lane & 7))*144)
                        + (unsigned)(lane >> 4)*16u;

    auto loadChunk = [&](int kc, int buf){
        const unsigned wbase = sbase + (unsigned)buf*(WBUF*4);
        const unsigned xbase = sbase + (unsigned)(2*WBUF*4) + (unsigned)buf*(XBUF*4);
        #pragma unroll
        for (int i = 0; i < 4; ++i){
            int idx = tid + i*256;
            int r = idx >> 2, c = idx & 3;
            cpa16s(wbase + (unsigned)(r*80 + c*16), W1 + (long)r*CC + kc*32 + c*8);
        }
        {
            int r = tid >> 3, c = tid & 7;
            cpa16s(xbase + (unsigned)(r*144 + c*16), Xh + (long)(kc*32 + r)*NN + n0 + c*8);
        }
        cpacommit();
    };

    loadChunk(0, 0);

    float acc[2][8][4];
    #pragma unroll
    for (int mt = 0; mt < 2; ++mt)
        #pragma unroll
        for (int nt = 0; nt < 8; ++nt)
            #pragma unroll
            for (int i = 0; i < 4; ++i) acc[mt][nt][i] = 0.f;
    float zr0 = 0.f, zr1 = 0.f;

    #pragma unroll 1
    for (int kc = 0; kc < 8; ++kc){
        cpawait0();
        __syncthreads();
        if (kc < 7) loadChunk(kc+1, (kc+1)&1);
        const unsigned wbuf = sbase + (unsigned)(kc&1)*(WBUF*4);
        const unsigned xbuf = sbase + (unsigned)(2*WBUF*4) + (unsigned)(kc&1)*(XBUF*4);
        if (ZFUSE && tid < 32){
            const unsigned* Xu = (const unsigned*)(sm + 2*WBUF + (kc&1)*XBUF);
            #pragma unroll
            for (int kk = 0; kk < 32; ++kk){
                float2 f = h2f(Xu[kk*XPITCH + tid]);
                zr0 = fmaf(f.x, KSs[kc*32 + kk], zr0);
                zr1 = fmaf(f.y, KSs[kc*32 + kk], zr1);
            }
        }
        #pragma unroll
        for (int s = 0; s < 2; ++s){
            unsigned a0[4], a1[4];
            ldsm4(a0, wbuf + aoff0 + (unsigned)s*32u);
            ldsm4(a1, wbuf + aoff1 + (unsigned)s*32u);
            const unsigned bbase = xbuf + boff + (unsigned)s*(16u*144u);
            #pragma unroll
            for (int ntp = 0; ntp < 4; ++ntp){
                unsigned bb[4];
                ldsm4t(bb, bbase + (unsigned)ntp*32u);
                mma16(acc[0][2*ntp  ], a0, bb[0], bb[1]);
                mma16(acc[1][2*ntp  ], a1, bb[0], bb[1]);
                mma16(acc[0][2*ntp+1], a0, bb[2], bb[3]);
                mma16(acc[1][2*ntp+1], a1, bb[2], bb[3]);
            }
        }
        __syncthreads();
    }

    if (ZFUSE){
        if (tid < 32){
            ZSs[2*tid]   = 1.0f / (zr0 + (float)NN);
            ZSs[2*tid+1] = 1.0f / (zr1 + (float)NN);
        }
        __syncthreads();
    }

    #pragma unroll
    for (int mt = 0; mt < 2; ++mt){
        const int r0 = w*32 + mt*16 + g;
        const int r1 = r0 + 8;
        float bi0 = 0.f, bi1 = 0.f;
        if (EPI != EATTN){
            const float* bb = p.B[y] + (p.bBatched ? b*CC : 0);
            bi0 = bb[r0]; bi1 = bb[r1];
        }
        #pragma unroll
        for (int nt = 0; nt < 8; ++nt){
            const int col = nt*8 + 2*lr;
            float x00 = acc[mt][nt][0] + bi0;
            float x01 = acc[mt][nt][1] + bi0;
            float x10 = acc[mt][nt][2] + bi1;
            float x11 = acc[mt][nt][3] + bi1;
            if (EPI == EATTN){
                const __half* Vb = p.Vp + (long)b*BCN;
                const __half* Gb = p.Gp + (long)b*BCN;
                float2 v0 = h2f(*(const unsigned*)(Vb + (long)r0*NN + n0 + col));
                float2 v1 = h2f(*(const unsigned*)(Vb + (long)r1*NN + n0 + col));
                float2 g0 = h2f(*(const unsigned*)(Gb + (long)r0*NN + n0 + col));
                float2 g1 = h2f(*(const unsigned*)(Gb + (long)r1*NN + n0 + col));
                float z0 = ZSs[col], z1 = ZSs[col+1];
                x00 = (x00 + v0.x) * z0 * g0.x;
                x01 = (x01 + v0.y) * z1 * g0.y;
                x10 = (x10 + v1.x) * z0 * g1.x;
                x11 = (x11 + v1.y) * z1 * g1.y;
            } else {
                x00 = epi_apply(EPI, x00); x01 = epi_apply(EPI, x01);
                x10 = epi_apply(EPI, x10); x11 = epi_apply(EPI, x11);
            }
            if (OUTF32){
                float* Yf = p.Yf + (long)b*BCN;
                *(float2*)(Yf + (long)r0*NN + n0 + col) = make_float2(x00, x01);
                *(float2*)(Yf + (long)r1*NN + n0 + col) = make_float2(x10, x11);
            } else {
                __half* Yh = p.Y[y] + (long)b*BCN;
                *(unsigned*)(Yh + (long)r0*NN + n0 + col) = packh(x00, x01);
                *(unsigned*)(Yh + (long)r1*NN + n0 + col) = packh(x10, x11);
            }
        }
    }
}

__global__ __launch_bounds__(256,2) void kv_kernel(
    const __half* __restrict__ K, const __half* __restrict__ V, float* __restrict__ P)
{
    extern __shared__ float sm[];
    const unsigned sbase = (unsigned)__cvta_generic_to_shared(sm);
    const int tid = threadIdx.x, w = tid >> 5, lane = tid & 31;
    const int g = lane >> 2, lr = lane & 3;
    const int wm = w & 3, wn = w >> 2;
    const int c0 = (blockIdx.x & 1) * 128;
    const int d0 = (blockIdx.x >> 1) * 128;
    const int chunk = blockIdx.y;
    const int b = blockIdx.z;
    const __half* Kb = K + (long)b*BCN;
    const __half* Vb = V + (long)b*BCN;
    const long nbase = (long)chunk * 1024;

    const unsigned kaoff0 = (unsigned)((wm*32 + (lane & 15))*KVPITCH)*4u + (unsigned)(lane >> 4)*16u;
    const unsigned kaoff1 = kaoff0 + (unsigned)(16*KVPITCH)*4u;
    const unsigned kboff  = (unsigned)((wn*64 + ((lane >> 4) & 1)*8 + (lane & 7))*KVPITCH)*4u
                          + (unsigned)((lane >> 3) & 1)*16u;

    auto loadChunk = [&](long nb, int buf){
        const unsigned abase = sbase + (unsigned)buf*(KVBUF*4);
        const unsigned bbase = sbase + (unsigned)(2*KVBUF*4) + (unsigned)buf*(KVBUF*4);
        #pragma unroll
        for (int i = 0; i < 2; ++i){
            int idx = tid + i*256;
            int r = idx >> 2, c8 = idx & 3;
            cpa16s(abase + (unsigned)(r*80 + c8*16), Kb + (long)(c0+r)*NN + nb + c8*8);
            cpa16s(bbase + (unsigned)(r*80 + c8*16), Vb + (long)(d0+r)*NN + nb + c8*8);
        }
        cpacommit();
    };

    loadChunk(nbase, 0);

    float acc[2][8][4];
    #pragma unroll
    for (int mt = 0; mt < 2; ++mt)
        #pragma unroll
        for (int nt = 0; nt < 8; ++nt)
            #pragma unroll
            for (int i = 0; i < 4; ++i) acc[mt][nt][i] = 0.f;

    #pragma unroll 1
    for (int it = 0; it < 32; ++it){
        cpawait0();
        __syncthreads();
        if (it < 31) loadChunk(nbase + (long)(it+1)*32, (it+1)&1);
        const unsigned abuf = sbase + (unsigned)(it&1)*(KVBUF*4);
        const unsigned bbuf = sbase + (unsigned)(2*KVBUF*4) + (unsigned)(it&1)*(KVBUF*4);
        #pragma unroll
        for (int s = 0; s < 2; ++s){
            const unsigned sb = (unsigned)s*32u;
            unsigned a0[4], a1[4];
            ldsm4(a0, abuf + kaoff0 + sb);
            ldsm4(a1, abuf + kaoff1 + sb);
            #pragma unroll
            for (int ntp = 0; ntp < 4; ++ntp){
                unsigned bb[4];
                ldsm4(bb, bbuf + kboff + (unsigned)(ntp*16*KVPITCH)*4u + sb);
                mma16(acc[0][2*ntp  ], a0, bb[0], bb[1]);
                mma16(acc[1][2*ntp  ], a1, bb[0], bb[1]);
                mma16(acc[0][2*ntp+1], a0, bb[2], bb[3]);
                mma16(acc[1][2*ntp+1], a1, bb[2], bb[3]);
            }
        }
        __syncthreads();
    }

    float* Pb = P + (long)(b*16 + chunk)*CC*CC;
    #pragma unroll
    for (int mt = 0; mt < 2; ++mt){
        #pragma unroll
        for (int half = 0; half < 2; ++half){
            const int r = c0 + wm*32 + mt*16 + g + half*8;
            #pragma unroll
            for (int nt = 0; nt < 8; ++nt){
                const int d = d0 + wn*64 + nt*8 + lr*2;
                float2 o;
                o.x = acc[mt][nt][half*2+0];
                o.y = acc[mt][nt][half*2+1];
                *(float2*)(Pb + (long)r*CC + d) = o;
            }
        }
    }
}

__global__ __launch_bounds__(256) void kvred_kernel(
    const float* __restrict__ P, __half* __restrict__ kvT)
{
    const int o = blockIdx.x * 256 + threadIdx.x;
    const int b = o >> 16;
    const int c = (o >> 8) & 255;
    const int d = o & 255;
    float s = 0.f;
    #pragma unroll
    for (int ch = 0; ch < 16; ++ch)
        s += P[((long)(b*16 + ch)*256 + c)*256 + d];
    kvT[((long)b*256 + d)*256 + c] = __float2half_rn(s * (1.0f/16.0f));
}

static const size_t HG_SMEM = (size_t)(2*WBUF + 2*XBUF + 320) * sizeof(float); // 51456
static const size_t KV_SMEM = (size_t)(4*KVBUF) * sizeof(float);

extern "C" void kernel_launch(void* const* d_in, const int* in_sizes, int n_in,
                              void* d_out, int out_size)
{
    (void)in_sizes; (void)n_in; (void)out_size;
    const float* x   = (const float*)d_in[0];
    const float* Wq1 = (const float*)d_in[1];  const float* bq1 = (const float*)d_in[2];
    const float* Wq2 = (const float*)d_in[3];  const float* bq2 = (const float*)d_in[4];
    const float* Wk1 = (const float*)d_in[5];  const float* bk1 = (const float*)d_in[6];
    const float* Wk2 = (const float*)d_in[7];  const float* bk2 = (const float*)d_in[8];
    const float* Wv  = (const float*)d_in[9];  const float* bv  = (const float*)d_in[10];
    const float* Wg  = (const float*)d_in[11]; const float* bg  = (const float*)d_in[12];
    const float* Wo  = (const float*)d_in[13]; const float* bo  = (const float*)d_in[14];
    float* out = (float*)d_out;

    __half *t, *t2, *q, *k, *v, *g, *xh, *wp16, *w16, *kvT16;
    float *kvp, *ks, *ab, *bp;
    cudaGetSymbolAddress((void**)&t,     g_t);
    cudaGetSymbolAddress((void**)&t2,    g_t2);
    cudaGetSymbolAddress((void**)&q,     g_q);
    cudaGetSymbolAddress((void**)&k,     g_k);
    cudaGetSymbolAddress((void**)&v,     g_v);
    cudaGetSymbolAddress((void**)&g,     g_g);
    cudaGetSymbolAddress((void**)&xh,    g_xh);
    cudaGetSymbolAddress((void**)&wp16,  g_wp16);
    cudaGetSymbolAddress((void**)&w16,   g_w16);
    cudaGetSymbolAddress((void**)&kvT16, g_kvT16);
    cudaGetSymbolAddress((void**)&kvp,   g_kvp);
    cudaGetSymbolAddress((void**)&ks,    g_ks);
    cudaGetSymbolAddress((void**)&ab,    g_ab);
    cudaGetSymbolAddress((void**)&bp,    g_bp);

    cudaFuncSetAttribute((const void*)hgemm_kernel<EGELU,0,0>,
                         cudaFuncAttributeMaxDynamicSharedMemorySize, (int)HG_SMEM);
    cudaFuncSetAttribute((const void*)hgemm_kernel<ESOFT,0,0>,
                         cudaFuncAttributeMaxDynamicSharedMemorySize, (int)HG_SMEM);
    cudaFuncSetAttribute((const void*)hgemm_kernel<EATTN,1,0>,
                         cudaFuncAttributeMaxDynamicSharedMemorySize, (int)HG_SMEM);
    cudaFuncSetAttribute((const void*)hgemm_kernel<EIDENT,0,1>,
                         cudaFuncAttributeMaxDynamicSharedMemorySize, (int)HG_SMEM);
    cudaFuncSetAttribute((const void*)kv_kernel,
                         cudaFuncAttributeMaxDynamicSharedMemorySize, (int)KV_SMEM);

    statspack_kernel<<<BB*CC, 256>>>(x, ab, xh);
    {
        WT wt;
        wt.W[0]=Wq1; wt.B[0]=bq1;
        wt.W[1]=Wk1; wt.B[1]=bk1;
        wt.W[2]=Wv;  wt.B[2]=bv;
        wt.W[3]=Wg;  wt.B[3]=bg;
        dim3 grid(4, BB, 4);
        wtrans_kernel<<<grid, 256>>>(wt, ab, wp16, bp);
    }
    {
        dim3 grid(64, 3);
        cvtw_kernel<<<grid, 256>>>(Wq2, Wk2, Wo, w16);
    }

    {   // stage-1 (gelu): q1->t, k1->t2, v, g
        TP p = {};
        p.W[0]=wp16 + 0L*BB*CC*CC; p.B[0]=bp + 0*BB*CC; p.X[0]=xh; p.Y[0]=t;
        p.W[1]=wp16 + 1L*BB*CC*CC; p.B[1]=bp + 1*BB*CC; p.X[1]=xh; p.Y[1]=t2;
        p.W[2]=wp16 + 2L*BB*CC*CC; p.B[2]=bp + 2*BB*CC; p.X[2]=xh; p.Y[2]=v;
        p.W[3]=wp16 + 3L*BB*CC*CC; p.B[3]=bp + 3*BB*CC; p.X[3]=xh; p.Y[3]=g;
        p.wBatched = 1; p.bBatched = 1;
        dim3 grid(NN/64, 4, BB);
        hgemm_kernel<EGELU,0,0><<<grid, 256, HG_SMEM>>>(p);
    }
    {   // stage-2 (softplus): q2: t->q, k2: t2->k
        TP p = {};
        p.W[0]=w16 + 0L*CC*CC; p.B[0]=bq2; p.X[0]=t;  p.Y[0]=q;
        p.W[1]=w16 + 1L*CC*CC; p.B[1]=bk2; p.X[1]=t2; p.Y[1]=k;
        p.wBatched = 0; p.bBatched = 0;
        dim3 grid(NN/64, 2, BB);
        hgemm_kernel<ESOFT,0,0><<<grid, 256, HG_SMEM>>>(p);
    }
    ksum_kernel<<<BB*CC, 256>>>(k, ks);
    {
        dim3 grid(4, 16, BB);
        kv_kernel<<<grid, 256, KV_SMEM>>>(k, v, kvp);
    }
    kvred_kernel<<<BB*CC, 256>>>(kvp, kvT16);
    {   // attn: t = (kvT.q + v) * z * g
        TP p = {};
        p.W[0]=kvT16; p.B[0]=nullptr; p.X[0]=q; p.Y[0]=t;
        p.Vp = v; p.Gp = g; p.ksp = ks;
        p.wBatched = 1; p.bBatched = 0;
        dim3 grid(NN/64, 1, BB);
        hgemm_kernel<EATTN,1,0><<<grid, 256, HG_SMEM>>>(p);
    }
    {   // final: out = Wo.t + bo (f32 out)
        TP p = {};
        p.W[0]=w16 + 2L*CC*CC; p.B[0]=bo; p.X[0]=t; p.Yf = out;
        p.wBatched = 0; p.bBatched = 0;
        dim3 grid(NN/64, 1, BB);
        hgemm_kernel<EIDENT,0,1><<<grid, 256, HG_SMEM>>>(p);
    }
}

// round 13
// speedup vs baseline: 1.0777x; 1.0558x over previous
#include <cuda_runtime.h>
#include <cuda_fp16.h>
#include <math.h>
#include <stdint.h>

#define CC 256
#define NN 16384
#define BB 4
#define BCN (CC*NN)
#define EGELU 0
#define ESOFT 1
#define EIDENT 2
#define EATTN 3
#define WPITCH 20
#define WBUF (128*WPITCH)          // 2560 words per buffer (128 rows)
#define BPITCH 72
#define BBUF (16*BPITCH)           // 1152 words per buffer
#define KVPITCH 20
#define KVBUF (128*KVPITCH)

__device__ __half g_t  [BB*BCN];   // paired [c2][n]
__device__ __half g_t2 [BB*BCN];   // paired
__device__ __half g_q  [BB*BCN];   // paired
__device__ __half g_k  [BB*BCN];   // plain [c][n]
__device__ __half g_v  [BB*BCN];   // plain
__device__ __half g_g  [BB*BCN];   // plain
__device__ __half g_xp [BB*BCN];   // paired
__device__ __half g_wp16[4*BB*CC*CC];
__device__ __half g_w16 [3*CC*CC];
__device__ __half g_kvT16[BB*CC*CC];
__device__ float  g_kvp[BB*16*CC*CC];
__device__ float  g_ks [BB*CC];
__device__ float  g_ab [2*BB*CC];
__device__ float  g_bp [4*BB*CC];

__device__ __forceinline__ void cpa16s(unsigned s, const void* g){
    asm volatile("cp.async.cg.shared.global [%0], [%1], 16;\n" :: "r"(s), "l"(g));
}
__device__ __forceinline__ void cpacommit(){ asm volatile("cp.async.commit_group;\n"); }
__device__ __forceinline__ void cpawait0(){ asm volatile("cp.async.wait_group 0;\n"); }
__device__ __forceinline__ void mma16(float* d, const unsigned* a, unsigned b0, unsigned b1){
    asm volatile(
      "mma.sync.aligned.m16n8k16.row.col.f32.f16.f16.f32 "
      "{%0,%1,%2,%3},{%4,%5,%6,%7},{%8,%9},{%0,%1,%2,%3};\n"
      : "+f"(d[0]), "+f"(d[1]), "+f"(d[2]), "+f"(d[3])
      : "r"(a[0]), "r"(a[1]), "r"(a[2]), "r"(a[3]), "r"(b0), "r"(b1));
}
__device__ __forceinline__ void ldsm4(unsigned* r, unsigned addr){
    asm volatile("ldmatrix.sync.aligned.m8n8.x4.shared.b16 {%0,%1,%2,%3}, [%4];"
        : "=r"(r[0]), "=r"(r[1]), "=r"(r[2]), "=r"(r[3]) : "r"(addr));
}
__device__ __forceinline__ unsigned packh(float lo, float hi){
    unsigned r;
    asm("cvt.rn.f16x2.f32 %0, %1, %2;" : "=r"(r) : "f"(hi), "f"(lo));
    return r;
}
__device__ __forceinline__ float2 h2f(unsigned u){
    __half2 h = *(__half2*)&u;
    return __half22float2(h);
}
__device__ __forceinline__ float geluf(float x){
    return 0.5f * x * (1.0f + erff(x * 0.70710678118654752440f));
}
__device__ __forceinline__ float softplusf(float x){
    return fmaxf(x, 0.0f) + log1pf(expf(-fabsf(x)));
}
__device__ __forceinline__ float epi_apply(int EPI, float x){
    if (EPI == EGELU) return geluf(x);
    if (EPI == ESOFT) return softplusf(x);
    return x;
}

// ---- merged norm-stats + fp16 pair-pack of x ---------------------------------
__global__ __launch_bounds__(256) void statspack_kernel(
    const float* __restrict__ x, float* __restrict__ ab, __half* __restrict__ xp)
{
    const int b = blockIdx.x >> 7, c2 = blockIdx.x & 127;
    const int tid = threadIdx.x;
    const float* r0 = x + ((long)b*CC + 2*c2)*NN;
    const float* r1 = r0 + NN;
    __half2* xo = (__half2*)xp + (long)(b*128 + c2)*NN;
    float s0=0.f, q0=0.f, s1=0.f, q1=0.f;
    #pragma unroll
    for (int i = 0; i < 16; ++i){
        int idx = (tid + i*256)*4;
        float4 a = *(const float4*)(r0 + idx);
        float4 c = *(const float4*)(r1 + idx);
        s0 += a.x+a.y+a.z+a.w;
        q0 += a.x*a.x + a.y*a.y + a.z*a.z + a.w*a.w;
        s1 += c.x+c.y+c.z+c.w;
        q1 += c.x*c.x + c.y*c.y + c.z*c.z + c.w*c.w;
        *(uint4*)(xo + idx) = make_uint4(packh(a.x,c.x), packh(a.y,c.y),
                                         packh(a.z,c.z), packh(a.w,c.w));
    }
    #pragma unroll
    for (int o = 16; o; o >>= 1){
        s0 += __shfl_xor_sync(0xffffffffu, s0, o);
        q0 += __shfl_xor_sync(0xffffffffu, q0, o);
        s1 += __shfl_xor_sync(0xffffffffu, s1, o);
        q1 += __shfl_xor_sync(0xffffffffu, q1, o);
    }
    __shared__ float sh[32];
    const int w = tid >> 5, lane = tid & 31;
    if (lane == 0){ sh[w] = s0; sh[8+w] = q0; sh[16+w] = s1; sh[24+w] = q1; }
    __syncthreads();
    if (tid < 2){
        float ts = 0.f, tq = 0.f;
        #pragma unroll
        for (int i = 0; i < 8; ++i){ ts += sh[tid*16 + i]; tq += sh[tid*16 + 8 + i]; }
        float mu  = ts * (1.0f/NN);
        float var = tq * (1.0f/NN) - mu*mu;
        float rs  = rsqrtf(var + 1e-5f);
        int c = 2*c2 + tid;
        ab[b*CC + c] = rs;
        ab[BB*CC + b*CC + c] = -mu*rs;
    }
}

struct WT { const float* W[4]; const float* B[4]; };
__global__ __launch_bounds__(256) void wtrans_kernel(
    WT p, const float* __restrict__ ab,
    __half* __restrict__ wp, float* __restrict__ bp)
{
    __shared__ float AL[256], BE[256];
    const int y = blockIdx.x, b = blockIdx.y, rg = blockIdx.z;
    const int tid = threadIdx.x, w = tid >> 5, lane = tid & 31;
    AL[tid] = ab[b*CC + tid];
    BE[tid] = ab[BB*CC + b*CC + tid];
    __syncthreads();
    const float* W = p.W[y];
    __half* wpo = wp + (long)(y*BB + b)*CC*CC;
    const int k0 = lane*8;
    #pragma unroll 1
    for (int pass = 0; pass < 8; ++pass){
        int m = rg*64 + pass*8 + w;
        const float* wr = W + (long)m*CC;
        float4 w0 = *(const float4*)(wr + k0);
        float4 w1 = *(const float4*)(wr + k0 + 4);
        float bacc = w0.x*BE[k0] + w0.y*BE[k0+1] + w0.z*BE[k0+2] + w0.w*BE[k0+3]
                   + w1.x*BE[k0+4] + w1.y*BE[k0+5] + w1.z*BE[k0+6] + w1.w*BE[k0+7];
        unsigned h0 = packh(w0.x*AL[k0],   w0.y*AL[k0+1]);
        unsigned h1 = packh(w0.z*AL[k0+2], w0.w*AL[k0+3]);
        unsigned h2 = packh(w1.x*AL[k0+4], w1.y*AL[k0+5]);
        unsigned h3 = packh(w1.z*AL[k0+6], w1.w*AL[k0+7]);
        *(uint4*)(wpo + (long)m*CC + k0) = make_uint4(h0,h1,h2,h3);
        #pragma unroll
        for (int o = 16; o; o >>= 1) bacc += __shfl_xor_sync(0xffffffffu, bacc, o);
        if (lane == 0) bp[(y*BB + b)*CC + m] = p.B[y][m] + bacc;
    }
}

__global__ __launch_bounds__(256) void cvtw_kernel(
    const float* __restrict__ W0, const float* __restrict__ W1,
    const float* __restrict__ W2, __half* __restrict__ outw)
{
    const float* Ws = (blockIdx.y == 0) ? W0 : (blockIdx.y == 1 ? W1 : W2);
    long i = ((long)blockIdx.x*256 + threadIdx.x)*4;
    float4 v = *(const float4*)(Ws + i);
    unsigned h0 = packh(v.x, v.y), h1 = packh(v.z, v.w);
    *(uint2*)(outw + (long)blockIdx.y*CC*CC + i) = make_uint2(h0, h1);
}

__global__ __launch_bounds__(256) void ksum_kernel(
    const __half* __restrict__ k, float* __restrict__ ks)
{
    const uint4* kp = (const uint4*)(k + (long)blockIdx.x*NN);
    const int tid = threadIdx.x;
    float s = 0.f;
    #pragma unroll
    for (int i = 0; i < 8; ++i){
        uint4 t = kp[tid + i*256];
        float2 f0 = h2f(t.x), f1 = h2f(t.y), f2 = h2f(t.z), f3 = h2f(t.w);
        s += f0.x+f0.y+f1.x+f1.y+f2.x+f2.y+f3.x+f3.y;
    }
    #pragma unroll
    for (int o = 16; o; o >>= 1) s += __shfl_xor_sync(0xffffffffu, s, o);
    __shared__ float sh[8];
    const int w = tid >> 5, lane = tid & 31;
    if (lane == 0) sh[w] = s;
    __syncthreads();
    if (tid == 0){
        float ts = 0.f;
        #pragma unroll
        for (int i = 0; i < 8; ++i) ts += sh[i];
        ks[blockIdx.x] = ts * (1.0f/16.0f);
    }
}

// ---- GEMM: M-tile 128 (blockIdx.y parity), N-tile 64; 8 warps = 4 rowgrp x 2 colhalf
struct TP {
    const __half* W[4]; const float* B[4];
    const __half* X[4];
    __half* Y[4];
    float* Yf;
    const __half* Vp; const __half* Gp; const float* ksp;
    int wBatched, bBatched, pairMask;
};

template<int EPI, int ZFUSE, int OUTF32>
__global__ __launch_bounds__(256,3) void hgemm_kernel(TP p)
{
    extern __shared__ float sm[];
    float* KSs = sm + 2*WBUF + 2*BBUF;
    float* ZSs = KSs + 256;
    const unsigned sbase = (unsigned)__cvta_generic_to_shared(sm);

    const int tid = threadIdx.x, w = tid >> 5, lane = tid & 31;
    const int g = lane >> 2, lr = lane & 3;
    const int wm = w & 3, wn = w >> 2;
    const int y = blockIdx.y >> 1;
    const int m0 = (blockIdx.y & 1) * 128;
    const int b = blockIdx.z;
    const long n0 = (long)blockIdx.x * 64;
    const __half* W1 = p.W[y] + (p.wBatched ? (long)b*CC*CC : 0) + (long)m0*CC;
    const __half2* X2 = (const __half2*)p.X[y] + (long)b*(BCN/2);

    if (ZFUSE) KSs[tid] = p.ksp[b*CC + tid];

    const unsigned aoff0 = (unsigned)((wm*32 + (lane & 15))*WPITCH)*4u + (unsigned)(lane >> 4)*16u;
    const unsigned aoff1 = aoff0 + (unsigned)(16*WPITCH)*4u;

    auto loadChunk = [&](int kc, int buf){
        const unsigned wbase = sbase + (unsigned)buf*(WBUF*4);
        const unsigned bbase = sbase + (unsigned)(2*WBUF*4) + (unsigned)buf*(BBUF*4);
        #pragma unroll
        for (int i = 0; i < 2; ++i){
            int idx = tid + i*256;
            int r = idx >> 2, c = idx & 3;
            cpa16s(wbase + (unsigned)(r*80 + c*16), W1 + (long)r*CC + kc*32 + c*8);
        }
        {
            int r = tid >> 4, c = tid & 15;
            cpa16s(bbase + (unsigned)(r*288 + c*16), X2 + (long)(kc*16 + r)*NN + n0 + c*4);
        }
        cpacommit();
    };

    loadChunk(0, 0);

    float acc[2][4][4];
    #pragma unroll
    for (int mt = 0; mt < 2; ++mt)
        #pragma unroll
        for (int nt = 0; nt < 4; ++nt)
            #pragma unroll
            for (int i = 0; i < 4; ++i) acc[mt][nt][i] = 0.f;
    float zreg = 0.f;

    #pragma unroll 1
    for (int kc = 0; kc < 8; ++kc){
        cpawait0();
        __syncthreads();
        if (kc < 7) loadChunk(kc+1, (kc+1)&1);
        const unsigned wbuf = sbase + (unsigned)(kc&1)*(WBUF*4);
        const unsigned* Bu = (const unsigned*)(sm + 2*WBUF + (kc&1)*BBUF);
        if (ZFUSE && tid < 64){
            #pragma unroll
            for (int kk = 0; kk < 16; ++kk){
                float2 f = h2f(Bu[kk*BPITCH + tid]);
                zreg = fmaf(f.x, KSs[kc*32 + 2*kk],     zreg);
                zreg = fmaf(f.y, KSs[kc*32 + 2*kk + 1], zreg);
            }
        }
        #pragma unroll
        for (int s = 0; s < 2; ++s){
            const int s8 = s*8;
            unsigned a0[4], a1[4];
            ldsm4(a0, wbuf + aoff0 + (unsigned)s8*4u);
            ldsm4(a1, wbuf + aoff1 + (unsigned)s8*4u);
            #pragma unroll
            for (int nt = 0; nt < 4; ++nt){
                unsigned b0 = Bu[(s8 + lr    )*BPITCH + wn*32 + nt*8 + g];
                unsigned b1 = Bu[(s8 + lr + 4)*BPITCH + wn*32 + nt*8 + g];
                mma16(acc[0][nt], a0, b0, b1);
                mma16(acc[1][nt], a1, b0, b1);
            }
        }
        __syncthreads();
    }

    if (ZFUSE){
        if (tid < 64) ZSs[tid] = 1.0f / (zreg + (float)NN);
        __syncthreads();
    }

    const int pair = (p.pairMask >> y) & 1;

    #pragma unroll
    for (int mt = 0; mt < 2; ++mt){
        const int r0 = m0 + wm*32 + mt*16 + g;
        const int r1 = r0 + 8;
        float bi0 = 0.f, bi1 = 0.f;
        if (EPI != EATTN){
            const float* bb = p.B[y] + (p.bBatched ? b*CC : 0);
            bi0 = bb[r0]; bi1 = bb[r1];
        }
        #pragma unroll
        for (int nt = 0; nt < 4; ++nt){
            const int col = wn*32 + nt*8 + 2*lr;
            float x00 = acc[mt][nt][0] + bi0;
            float x01 = acc[mt][nt][1] + bi0;
            float x10 = acc[mt][nt][2] + bi1;
            float x11 = acc[mt][nt][3] + bi1;
            if (EPI == EATTN){
                const __half* Vb = p.Vp + (long)b*BCN;
                const __half* Gb = p.Gp + (long)b*BCN;
                float2 v0 = h2f(*(const unsigned*)(Vb + (long)r0*NN + n0 + col));
                float2 v1 = h2f(*(const unsigned*)(Vb + (long)r1*NN + n0 + col));
                float2 g0 = h2f(*(const unsigned*)(Gb + (long)r0*NN + n0 + col));
                float2 g1 = h2f(*(const unsigned*)(Gb + (long)r1*NN + n0 + col));
                float z0 = ZSs[col], z1 = ZSs[col+1];
                x00 = (x00 + v0.x) * z0 * g0.x;
                x01 = (x01 + v0.y) * z1 * g0.y;
                x10 = (x10 + v1.x) * z0 * g1.x;
                x11 = (x11 + v1.y) * z1 * g1.y;
            } else {
                x00 = epi_apply(EPI, x00); x01 = epi_apply(EPI, x01);
                x10 = epi_apply(EPI, x10); x11 = epi_apply(EPI, x11);
            }
            if (OUTF32){
                float* Yf = p.Yf + (long)b*BCN;
                *(float2*)(Yf + (long)r0*NN + n0 + col) = make_float2(x00, x01);
                *(float2*)(Yf + (long)r1*NN + n0 + col) = make_float2(x10, x11);
            } else if (pair){
                float u00 = __shfl_down_sync(0xffffffffu, x00, 4);
                float u01 = __shfl_down_sync(0xffffffffu, x01, 4);
                float u10 = __shfl_down_sync(0xffffffffu, x10, 4);
                float u11 = __shfl_down_sync(0xffffffffu, x11, 4);
                if (!(g & 1)){
                    __half2* Y2 = (__half2*)p.Y[y] + (long)b*(BCN/2);
                    *(uint2*)(Y2 + (long)(r0>>1)*NN + n0 + col) =
                        make_uint2(packh(x00, u00), packh(x01, u01));
                    *(uint2*)(Y2 + (long)(r1>>1)*NN + n0 + col) =
                        make_uint2(packh(x10, u10), packh(x11, u11));
                }
            } else {
                __half* Yh = p.Y[y] + (long)b*BCN;
                *(unsigned*)(Yh + (long)r0*NN + n0 + col) = packh(x00, x01);
                *(unsigned*)(Yh + (long)r1*NN + n0 + col) = packh(x10, x11);
            }
        }
    }
}

__global__ __launch_bounds__(256,2) void kv_kernel(
    const __half* __restrict__ K, const __half* __restrict__ V, float* __restrict__ P)
{
    extern __shared__ float sm[];
    const unsigned sbase = (unsigned)__cvta_generic_to_shared(sm);
    const int tid = threadIdx.x, w = tid >> 5, lane = tid & 31;
    const int g = lane >> 2, lr = lane & 3;
    const int wm = w & 3, wn = w >> 2;
    const int c0 = (blockIdx.x & 1) * 128;
    const int d0 = (blockIdx.x >> 1) * 128;
    const int chunk = blockIdx.y;
    const int b = blockIdx.z;
    const __half* Kb = K + (long)b*BCN;
    const __half* Vb = V + (long)b*BCN;
    const long nbase = (long)chunk * 1024;

    const unsigned kaoff0 = (unsigned)((wm*32 + (lane & 15))*KVPITCH)*4u + (unsigned)(lane >> 4)*16u;
    const unsigned kaoff1 = kaoff0 + (unsigned)(16*KVPITCH)*4u;
    const unsigned kboff  = (unsigned)((wn*64 + ((lane >> 4) & 1)*8 + (lane & 7))*KVPITCH)*4u
                          + (unsigned)((lane >> 3) & 1)*16u;

    auto loadChunk = [&](long nb, int buf){
        const unsigned abase = sbase + (unsigned)buf*(KVBUF*4);
        const unsigned bbase = sbase + (unsigned)(2*KVBUF*4) + (unsigned)buf*(KVBUF*4);
        #pragma unroll
        for (int i = 0; i < 2; ++i){
            int idx = tid + i*256;
            int r = idx >> 2, c8 = idx & 3;
            cpa16s(abase + (unsigned)(r*80 + c8*16), Kb + (long)(c0+r)*NN + nb + c8*8);
            cpa16s(bbase + (unsigned)(r*80 + c8*16), Vb + (long)(d0+r)*NN + nb + c8*8);
        }
        cpacommit();
    };

    loadChunk(nbase, 0);

    float acc[2][8][4];
    #pragma unroll
    for (int mt = 0; mt < 2; ++mt)
        #pragma unroll
        for (int nt = 0; nt < 8; ++nt)
            #pragma unroll
            for (int i = 0; i < 4; ++i) acc[mt][nt][i] = 0.f;

    #pragma unroll 1
    for (int it = 0; it < 32; ++it){
        cpawait0();
        __syncthreads();
        if (it < 31) loadChunk(nbase + (long)(it+1)*32, (it+1)&1);
        const unsigned abuf = sbase + (unsigned)(it&1)*(KVBUF*4);
        const unsigned bbuf = sbase + (unsigned)(2*KVBUF*4) + (unsigned)(it&1)*(KVBUF*4);
        #pragma unroll
        for (int s = 0; s < 2; ++s){
            const unsigned sb = (unsigned)s*32u;
            unsigned a0[4], a1[4];
            ldsm4(a0, abuf + kaoff0 + sb);
            ldsm4(a1, abuf + kaoff1 + sb);
            #pragma unroll
            for (int ntp = 0; ntp < 4; ++ntp){
                unsigned bb[4];
                ldsm4(bb, bbuf + kboff + (unsigned)(ntp*16*KVPITCH)*4u + sb);
                mma16(acc[0][2*ntp  ], a0, bb[0], bb[1]);
                mma16(acc[1][2*ntp  ], a1, bb[0], bb[1]);
                mma16(acc[0][2*ntp+1], a0, bb[2], bb[3]);
                mma16(acc[1][2*ntp+1], a1, bb[2], bb[3]);
            }
        }
        __syncthreads();
    }

    float* Pb = P + (long)(b*16 + chunk)*CC*CC;
    #pragma unroll
    for (int mt = 0; mt < 2; ++mt){
        #pragma unroll
        for (int half = 0; half < 2; ++half){
            const int r = c0 + wm*32 + mt*16 + g + half*8;
            #pragma unroll
            for (int nt = 0; nt < 8; ++nt){
                const int d = d0 + wn*64 + nt*8 + lr*2;
                float2 o;
                o.x = acc[mt][nt][half*2+0];
                o.y = acc[mt][nt][half*2+1];
                *(float2*)(Pb + (long)r*CC + d) = o;
            }
        }
    }
}

__global__ __launch_bounds__(256) void kvred_kernel(
    const float* __restrict__ P, __half* __restrict__ kvT)
{
    const int o = blockIdx.x * 256 + threadIdx.x;
    const int b = o >> 16;
    const int c = (o >> 8) & 255;
    const int d = o & 255;
    float s = 0.f;
    #pragma unroll
    for (int ch = 0; ch < 16; ++ch)
        s += P[((long)(b*16 + ch)*256 + c)*256 + d];
    kvT[((long)b*256 + d)*256 + c] = __float2half_rn(s * (1.0f/16.0f));
}

static const size_t HG_SMEM = (size_t)(2*WBUF + 2*BBUF + 320) * sizeof(float); // 30976
static const size_t KV_SMEM = (size_t)(4*KVBUF) * sizeof(float);

extern "C" void kernel_launch(void* const* d_in, const int* in_sizes, int n_in,
                              void* d_out, int out_size)
{
    (void)in_sizes; (void)n_in; (void)out_size;
    const float* x   = (const float*)d_in[0];
    const float* Wq1 = (const float*)d_in[1];  const float* bq1 = (const float*)d_in[2];
    const float* Wq2 = (const float*)d_in[3];  const float* bq2 = (const float*)d_in[4];
    const float* Wk1 = (const float*)d_in[5];  const float* bk1 = (const float*)d_in[6];
    const float* Wk2 = (const float*)d_in[7];  const float* bk2 = (const float*)d_in[8];
    const float* Wv  = (const float*)d_in[9];  const float* bv  = (const float*)d_in[10];
    const float* Wg  = (const float*)d_in[11]; const float* bg  = (const float*)d_in[12];
    const float* Wo  = (const float*)d_in[13]; const float* bo  = (const float*)d_in[14];
    float* out = (float*)d_out;

    __half *t, *t2, *q, *k, *v, *g, *xp, *wp16, *w16, *kvT16;
    float *kvp, *ks, *ab, *bp;
    cudaGetSymbolAddress((void**)&t,     g_t);
    cudaGetSymbolAddress((void**)&t2,    g_t2);
    cudaGetSymbolAddress((void**)&q,     g_q);
    cudaGetSymbolAddress((void**)&k,     g_k);
    cudaGetSymbolAddress((void**)&v,     g_v);
    cudaGetSymbolAddress((void**)&g,     g_g);
    cudaGetSymbolAddress((void**)&xp,    g_xp);
    cudaGetSymbolAddress((void**)&wp16,  g_wp16);
    cudaGetSymbolAddress((void**)&w16,   g_w16);
    cudaGetSymbolAddress((void**)&kvT16, g_kvT16);
    cudaGetSymbolAddress((void**)&kvp,   g_kvp);
    cudaGetSymbolAddress((void**)&ks,    g_ks);
    cudaGetSymbolAddress((void**)&ab,    g_ab);
    cudaGetSymbolAddress((void**)&bp,    g_bp);

    cudaFuncSetAttribute((const void*)hgemm_kernel<EGELU,0,0>,
                         cudaFuncAttributeMaxDynamicSharedMemorySize, (int)HG_SMEM);
    cudaFuncSetAttribute((const void*)hgemm_kernel<ESOFT,0,0>,
                         cudaFuncAttributeMaxDynamicSharedMemorySize, (int)HG_SMEM);
    cudaFuncSetAttribute((const void*)hgemm_kernel<EATTN,1,0>,
                         cudaFuncAttributeMaxDynamicSharedMemorySize, (int)HG_SMEM);
    cudaFuncSetAttribute((const void*)hgemm_kernel<EIDENT,0,1>,
                         cudaFuncAttributeMaxDynamicSharedMemorySize, (int)HG_SMEM);
    cudaFuncSetAttribute((const void*)kv_kernel,
                         cudaFuncAttributeMaxDynamicSharedMemorySize, (int)KV_SMEM);

    statspack_kernel<<<BB*128, 256>>>(x, ab, xp);
    {
        WT wt;
        wt.W[0]=Wq1; wt.B[0]=bq1;
        wt.W[1]=Wk1; wt.B[1]=bk1;
        wt.W[2]=Wv;  wt.B[2]=bv;
        wt.W[3]=Wg;  wt.B[3]=bg;
        dim3 grid(4, BB, 4);
        wtrans_kernel<<<grid, 256>>>(wt, ab, wp16, bp);
    }
    {
        dim3 grid(64, 3);
        cvtw_kernel<<<grid, 256>>>(Wq2, Wk2, Wo, w16);
    }

    {   // stage-1 (gelu): q1->t(pair), k1->t2(pair), v(plain), g(plain)
        TP p = {};
        p.W[0]=wp16 + 0L*BB*CC*CC; p.B[0]=bp + 0*BB*CC; p.X[0]=xp; p.Y[0]=t;
        p.W[1]=wp16 + 1L*BB*CC*CC; p.B[1]=bp + 1*BB*CC; p.X[1]=xp; p.Y[1]=t2;
        p.W[2]=wp16 + 2L*BB*CC*CC; p.B[2]=bp + 2*BB*CC; p.X[2]=xp; p.Y[2]=v;
        p.W[3]=wp16 + 3L*BB*CC*CC; p.B[3]=bp + 3*BB*CC; p.X[3]=xp; p.Y[3]=g;
        p.wBatched = 1; p.bBatched = 1; p.pairMask = 0b0011;
        dim3 grid(NN/64, 8, BB);
        hgemm_kernel<EGELU,0,0><<<grid, 256, HG_SMEM>>>(p);
    }
    {   // stage-2 (softplus): q2: t->q(pair), k2: t2->k(plain)
        TP p = {};
        p.W[0]=w16 + 0L*CC*CC; p.B[0]=bq2; p.X[0]=t;  p.Y[0]=q;
        p.W[1]=w16 + 1L*CC*CC; p.B[1]=bk2; p.X[1]=t2; p.Y[1]=k;
        p.wBatched = 0; p.bBatched = 0; p.pairMask = 0b01;
        dim3 grid(NN/64, 4, BB);
        hgemm_kernel<ESOFT,0,0><<<grid, 256, HG_SMEM>>>(p);
    }
    ksum_kernel<<<BB*CC, 256>>>(k, ks);
    {
        dim3 grid(4, 16, BB);
        kv_kernel<<<grid, 256, KV_SMEM>>>(k, v, kvp);
    }
    kvred_kernel<<<BB*CC, 256>>>(kvp, kvT16);
    {   // attn: t = (kvT.q + v) * z * g   (paired out)
        TP p = {};
        p.W[0]=kvT16; p.B[0]=nullptr; p.X[0]=q; p.Y[0]=t;
        p.Vp = v; p.Gp = g; p.ksp = ks;
        p.wBatched = 1; p.bBatched = 0; p.pairMask = 0b1;
        dim3 grid(NN/64, 2, BB);
        hgemm_kernel<EATTN,1,0><<<grid, 256, HG_SMEM>>>(p);
    }
    {   // final: out = Wo.t + bo (f32 out)
        TP p = {};
        p.W[0]=w16 + 2L*CC*CC; p.B[0]=bo; p.X[0]=t; p.Yf = out;
        p.wBatched = 0; p.bBatched = 0; p.pairMask = 0;
        dim3 grid(NN/64, 2, BB);
        hgemm_kernel<EIDENT,0,1><<<grid, 256, HG_SMEM>>>(p);
    }
}

// round 14
// speedup vs baseline: 1.1372x; 1.0552x over previous
#include <cuda_runtime.h>
#include <cuda_fp16.h>
#include <math.h>
#include <stdint.h>

#define CC 256
#define NN 16384
#define BB 4
#define BCN (CC*NN)
#define EGELU 0
#define ESOFT 1
#define EIDENT 2
#define EATTN 3
#define WPITCH 20
#define WBUF (128*WPITCH)          // 2560 words per buffer (128 rows)
#define BPITCH 72
#define BBUF (16*BPITCH)           // 1152 words per buffer
#define KVPITCH 20
#define KVBUF (128*KVPITCH)

__device__ __half g_t  [BB*BCN];   // paired [c2][n]
__device__ __half g_t2 [BB*BCN];   // paired
__device__ __half g_q  [BB*BCN];   // paired
__device__ __half g_k  [BB*BCN];   // plain [c][n]
__device__ __half g_v  [BB*BCN];   // plain
__device__ __half g_g  [BB*BCN];   // plain
__device__ __half g_xp [BB*BCN];   // paired
__device__ __half g_wp16[4*BB*CC*CC];
__device__ __half g_w16 [3*CC*CC];
__device__ __half g_kvT16[BB*CC*CC];
__device__ float  g_kvp[BB*16*CC*CC];
__device__ float  g_ks [BB*CC];
__device__ float  g_ab [2*BB*CC];
__device__ float  g_bp [4*BB*CC];

__device__ __forceinline__ void cpa16s(unsigned s, const void* g){
    asm volatile("cp.async.cg.shared.global [%0], [%1], 16;\n" :: "r"(s), "l"(g));
}
__device__ __forceinline__ void cpacommit(){ asm volatile("cp.async.commit_group;\n"); }
__device__ __forceinline__ void cpawait0(){ asm volatile("cp.async.wait_group 0;\n"); }
__device__ __forceinline__ void cpawait1(){ asm volatile("cp.async.wait_group 1;\n"); }
__device__ __forceinline__ void mma16(float* d, const unsigned* a, unsigned b0, unsigned b1){
    asm volatile(
      "mma.sync.aligned.m16n8k16.row.col.f32.f16.f16.f32 "
      "{%0,%1,%2,%3},{%4,%5,%6,%7},{%8,%9},{%0,%1,%2,%3};\n"
      : "+f"(d[0]), "+f"(d[1]), "+f"(d[2]), "+f"(d[3])
      : "r"(a[0]), "r"(a[1]), "r"(a[2]), "r"(a[3]), "r"(b0), "r"(b1));
}
__device__ __forceinline__ void ldsm4(unsigned* r, unsigned addr){
    asm volatile("ldmatrix.sync.aligned.m8n8.x4.shared.b16 {%0,%1,%2,%3}, [%4];"
        : "=r"(r[0]), "=r"(r[1]), "=r"(r[2]), "=r"(r[3]) : "r"(addr));
}
__device__ __forceinline__ unsigned packh(float lo, float hi){
    unsigned r;
    asm("cvt.rn.f16x2.f32 %0, %1, %2;" : "=r"(r) : "f"(hi), "f"(lo));
    return r;
}
__device__ __forceinline__ float2 h2f(unsigned u){
    __half2 h = *(__half2*)&u;
    return __half22float2(h);
}
__device__ __forceinline__ float geluf(float x){
    return 0.5f * x * (1.0f + erff(x * 0.70710678118654752440f));
}
__device__ __forceinline__ float softplusf(float x){
    return fmaxf(x, 0.0f) + log1pf(expf(-fabsf(x)));
}
__device__ __forceinline__ float epi_apply(int EPI, float x){
    if (EPI == EGELU) return geluf(x);
    if (EPI == ESOFT) return softplusf(x);
    return x;
}

// ---- merged norm-stats + fp16 pair-pack of x ---------------------------------
__global__ __launch_bounds__(256) void statspack_kernel(
    const float* __restrict__ x, float* __restrict__ ab, __half* __restrict__ xp)
{
    const int b = blockIdx.x >> 7, c2 = blockIdx.x & 127;
    const int tid = threadIdx.x;
    const float* r0 = x + ((long)b*CC + 2*c2)*NN;
    const float* r1 = r0 + NN;
    __half2* xo = (__half2*)xp + (long)(b*128 + c2)*NN;
    float s0=0.f, q0=0.f, s1=0.f, q1=0.f;
    #pragma unroll
    for (int i = 0; i < 16; ++i){
        int idx = (tid + i*256)*4;
        float4 a = *(const float4*)(r0 + idx);
        float4 c = *(const float4*)(r1 + idx);
        s0 += a.x+a.y+a.z+a.w;
        q0 += a.x*a.x + a.y*a.y + a.z*a.z + a.w*a.w;
        s1 += c.x+c.y+c.z+c.w;
        q1 += c.x*c.x + c.y*c.y + c.z*c.z + c.w*c.w;
        *(uint4*)(xo + idx) = make_uint4(packh(a.x,c.x), packh(a.y,c.y),
                                         packh(a.z,c.z), packh(a.w,c.w));
    }
    #pragma unroll
    for (int o = 16; o; o >>= 1){
        s0 += __shfl_xor_sync(0xffffffffu, s0, o);
        q0 += __shfl_xor_sync(0xffffffffu, q0, o);
        s1 += __shfl_xor_sync(0xffffffffu, s1, o);
        q1 += __shfl_xor_sync(0xffffffffu, q1, o);
    }
    __shared__ float sh[32];
    const int w = tid >> 5, lane = tid & 31;
    if (lane == 0){ sh[w] = s0; sh[8+w] = q0; sh[16+w] = s1; sh[24+w] = q1; }
    __syncthreads();
    if (tid < 2){
        float ts = 0.f, tq = 0.f;
        #pragma unroll
        for (int i = 0; i < 8; ++i){ ts += sh[tid*16 + i]; tq += sh[tid*16 + 8 + i]; }
        float mu  = ts * (1.0f/NN);
        float var = tq * (1.0f/NN) - mu*mu;
        float rs  = rsqrtf(var + 1e-5f);
        int c = 2*c2 + tid;
        ab[b*CC + c] = rs;
        ab[BB*CC + b*CC + c] = -mu*rs;
    }
}

struct WT { const float* W[4]; const float* B[4]; };
__global__ __launch_bounds__(256) void wtrans_kernel(
    WT p, const float* __restrict__ ab,
    __half* __restrict__ wp, float* __restrict__ bp)
{
    __shared__ float AL[256], BE[256];
    const int y = blockIdx.x, b = blockIdx.y, rg = blockIdx.z;
    const int tid = threadIdx.x, w = tid >> 5, lane = tid & 31;
    AL[tid] = ab[b*CC + tid];
    BE[tid] = ab[BB*CC + b*CC + tid];
    __syncthreads();
    const float* W = p.W[y];
    __half* wpo = wp + (long)(y*BB + b)*CC*CC;
    const int k0 = lane*8;
    #pragma unroll 1
    for (int pass = 0; pass < 8; ++pass){
        int m = rg*64 + pass*8 + w;
        const float* wr = W + (long)m*CC;
        float4 w0 = *(const float4*)(wr + k0);
        float4 w1 = *(const float4*)(wr + k0 + 4);
        float bacc = w0.x*BE[k0] + w0.y*BE[k0+1] + w0.z*BE[k0+2] + w0.w*BE[k0+3]
                   + w1.x*BE[k0+4] + w1.y*BE[k0+5] + w1.z*BE[k0+6] + w1.w*BE[k0+7];
        unsigned h0 = packh(w0.x*AL[k0],   w0.y*AL[k0+1]);
        unsigned h1 = packh(w0.z*AL[k0+2], w0.w*AL[k0+3]);
        unsigned h2 = packh(w1.x*AL[k0+4], w1.y*AL[k0+5]);
        unsigned h3 = packh(w1.z*AL[k0+6], w1.w*AL[k0+7]);
        *(uint4*)(wpo + (long)m*CC + k0) = make_uint4(h0,h1,h2,h3);
        #pragma unroll
        for (int o = 16; o; o >>= 1) bacc += __shfl_xor_sync(0xffffffffu, bacc, o);
        if (lane == 0) bp[(y*BB + b)*CC + m] = p.B[y][m] + bacc;
    }
}

__global__ __launch_bounds__(256) void cvtw_kernel(
    const float* __restrict__ W0, const float* __restrict__ W1,
    const float* __restrict__ W2, __half* __restrict__ outw)
{
    const float* Ws = (blockIdx.y == 0) ? W0 : (blockIdx.y == 1 ? W1 : W2);
    long i = ((long)blockIdx.x*256 + threadIdx.x)*4;
    float4 v = *(const float4*)(Ws + i);
    unsigned h0 = packh(v.x, v.y), h1 = packh(v.z, v.w);
    *(uint2*)(outw + (long)blockIdx.y*CC*CC + i) = make_uint2(h0, h1);
}

__global__ __launch_bounds__(256) void ksum_kernel(
    const __half* __restrict__ k, float* __restrict__ ks)
{
    const uint4* kp = (const uint4*)(k + (long)blockIdx.x*NN);
    const int tid = threadIdx.x;
    float s = 0.f;
    #pragma unroll
    for (int i = 0; i < 8; ++i){
        uint4 t = kp[tid + i*256];
        float2 f0 = h2f(t.x), f1 = h2f(t.y), f2 = h2f(t.z), f3 = h2f(t.w);
        s += f0.x+f0.y+f1.x+f1.y+f2.x+f2.y+f3.x+f3.y;
    }
    #pragma unroll
    for (int o = 16; o; o >>= 1) s += __shfl_xor_sync(0xffffffffu, s, o);
    __shared__ float sh[8];
    const int w = tid >> 5, lane = tid & 31;
    if (lane == 0) sh[w] = s;
    __syncthreads();
    if (tid == 0){
        float ts = 0.f;
        #pragma unroll
        for (int i = 0; i < 8; ++i) ts += sh[i];
        ks[blockIdx.x] = ts * (1.0f/16.0f);
    }
}

// ---- GEMM: M-tile 128, N-tile 64; 8 warps = 4 rowgrp x 2 colhalf; 3-stage pipe
struct TP {
    const __half* W[4]; const float* B[4];
    const __half* X[4];
    __half* Y[4];
    float* Yf;
    const __half* Vp; const __half* Gp; const float* ksp;
    int wBatched, bBatched, pairMask;
};

template<int EPI, int ZFUSE, int OUTF32>
__global__ __launch_bounds__(256,3) void hgemm_kernel(TP p)
{
    extern __shared__ float sm[];
    float* KSs = sm + 3*WBUF + 3*BBUF;
    float* ZSs = KSs + 256;
    const unsigned sbase = (unsigned)__cvta_generic_to_shared(sm);

    const int tid = threadIdx.x, w = tid >> 5, lane = tid & 31;
    const int g = lane >> 2, lr = lane & 3;
    const int wm = w & 3, wn = w >> 2;
    const int y = blockIdx.y >> 1;
    const int m0 = (blockIdx.y & 1) * 128;
    const int b = blockIdx.z;
    const long n0 = (long)blockIdx.x * 64;
    const __half* W1 = p.W[y] + (p.wBatched ? (long)b*CC*CC : 0) + (long)m0*CC;
    const __half2* X2 = (const __half2*)p.X[y] + (long)b*(BCN/2);

    if (ZFUSE) KSs[tid] = p.ksp[b*CC + tid];

    const unsigned aoff0 = (unsigned)((wm*32 + (lane & 15))*WPITCH)*4u + (unsigned)(lane >> 4)*16u;
    const unsigned aoff1 = aoff0 + (unsigned)(16*WPITCH)*4u;

    auto loadChunk = [&](int kc, int buf){
        const unsigned wbase = sbase + (unsigned)buf*(WBUF*4);
        const unsigned bbase = sbase + (unsigned)(3*WBUF*4) + (unsigned)buf*(BBUF*4);
        #pragma unroll
        for (int i = 0; i < 2; ++i){
            int idx = tid + i*256;
            int r = idx >> 2, c = idx & 3;
            cpa16s(wbase + (unsigned)(r*80 + c*16), W1 + (long)r*CC + kc*32 + c*8);
        }
        {
            int r = tid >> 4, c = tid & 15;
            cpa16s(bbase + (unsigned)(r*288 + c*16), X2 + (long)(kc*16 + r)*NN + n0 + c*4);
        }
        cpacommit();
    };

    loadChunk(0, 0);
    loadChunk(1, 1);

    float acc[2][4][4];
    #pragma unroll
    for (int mt = 0; mt < 2; ++mt)
        #pragma unroll
        for (int nt = 0; nt < 4; ++nt)
            #pragma unroll
            for (int i = 0; i < 4; ++i) acc[mt][nt][i] = 0.f;
    float zreg = 0.f;

    int buf = 0;
    #pragma unroll 1
    for (int kc = 0; kc < 8; ++kc){
        if (kc < 7) cpawait1(); else cpawait0();
        __syncthreads();
        if (kc < 6){
            int nb = buf + 2; if (nb >= 3) nb -= 3;
            loadChunk(kc+2, nb);
        }
        const unsigned wbuf = sbase + (unsigned)buf*(WBUF*4);
        const unsigned* Bu = (const unsigned*)(sm + 3*WBUF + buf*BBUF);
        if (ZFUSE && tid < 64){
            #pragma unroll
            for (int kk = 0; kk < 16; ++kk){
                float2 f = h2f(Bu[kk*BPITCH + tid]);
                zreg = fmaf(f.x, KSs[kc*32 + 2*kk],     zreg);
                zreg = fmaf(f.y, KSs[kc*32 + 2*kk + 1], zreg);
            }
        }
        #pragma unroll
        for (int s = 0; s < 2; ++s){
            const int s8 = s*8;
            unsigned a0[4], a1[4];
            ldsm4(a0, wbuf + aoff0 + (unsigned)s8*4u);
            ldsm4(a1, wbuf + aoff1 + (unsigned)s8*4u);
            #pragma unroll
            for (int nt = 0; nt < 4; ++nt){
                unsigned b0 = Bu[(s8 + lr    )*BPITCH + wn*32 + nt*8 + g];
                unsigned b1 = Bu[(s8 + lr + 4)*BPITCH + wn*32 + nt*8 + g];
                mma16(acc[0][nt], a0, b0, b1);
                mma16(acc[1][nt], a1, b0, b1);
            }
        }
        if (++buf == 3) buf = 0;
    }

    if (ZFUSE){
        __syncthreads();
        if (tid < 64) ZSs[tid] = 1.0f / (zreg + (float)NN);
        __syncthreads();
    }

    const int pair = (p.pairMask >> y) & 1;

    #pragma unroll
    for (int mt = 0; mt < 2; ++mt){
        const int r0 = m0 + wm*32 + mt*16 + g;
        const int r1 = r0 + 8;
        float bi0 = 0.f, bi1 = 0.f;
        if (EPI != EATTN){
            const float* bb = p.B[y] + (p.bBatched ? b*CC : 0);
            bi0 = bb[r0]; bi1 = bb[r1];
        }
        #pragma unroll
        for (int nt = 0; nt < 4; ++nt){
            const int col = wn*32 + nt*8 + 2*lr;
            float x00 = acc[mt][nt][0] + bi0;
            float x01 = acc[mt][nt][1] + bi0;
            float x10 = acc[mt][nt][2] + bi1;
            float x11 = acc[mt][nt][3] + bi1;
            if (EPI == EATTN){
                const __half* Vb = p.Vp + (long)b*BCN;
                const __half* Gb = p.Gp + (long)b*BCN;
                float2 v0 = h2f(*(const unsigned*)(Vb + (long)r0*NN + n0 + col));
                float2 v1 = h2f(*(const unsigned*)(Vb + (long)r1*NN + n0 + col));
                float2 g0 = h2f(*(const unsigned*)(Gb + (long)r0*NN + n0 + col));
                float2 g1 = h2f(*(const unsigned*)(Gb + (long)r1*NN + n0 + col));
                float z0 = ZSs[col], z1 = ZSs[col+1];
                x00 = (x00 + v0.x) * z0 * g0.x;
                x01 = (x01 + v0.y) * z1 * g0.y;
                x10 = (x10 + v1.x) * z0 * g1.x;
                x11 = (x11 + v1.y) * z1 * g1.y;
            } else {
                x00 = epi_apply(EPI, x00); x01 = epi_apply(EPI, x01);
                x10 = epi_apply(EPI, x10); x11 = epi_apply(EPI, x11);
            }
            if (OUTF32){
                float* Yf = p.Yf + (long)b*BCN;
                *(float2*)(Yf + (long)r0*NN + n0 + col) = make_float2(x00, x01);
                *(float2*)(Yf + (long)r1*NN + n0 + col) = make_float2(x10, x11);
            } else if (pair){
                float u00 = __shfl_down_sync(0xffffffffu, x00, 4);
                float u01 = __shfl_down_sync(0xffffffffu, x01, 4);
                float u10 = __shfl_down_sync(0xffffffffu, x10, 4);
                float u11 = __shfl_down_sync(0xffffffffu, x11, 4);
                if (!(g & 1)){
                    __half2* Y2 = (__half2*)p.Y[y] + (long)b*(BCN/2);
                    *(uint2*)(Y2 + (long)(r0>>1)*NN + n0 + col) =
                        make_uint2(packh(x00, u00), packh(x01, u01));
                    *(uint2*)(Y2 + (long)(r1>>1)*NN + n0 + col) =
                        make_uint2(packh(x10, u10), packh(x11, u11));
                }
            } else {
                __half* Yh = p.Y[y] + (long)b*BCN;
                *(unsigned*)(Yh + (long)r0*NN + n0 + col) = packh(x00, x01);
                *(unsigned*)(Yh + (long)r1*NN + n0 + col) = packh(x10, x11);
            }
        }
    }
}

// ---- kv partial GEMM: 3-stage pipeline, single barrier per chunk -------------
__global__ __launch_bounds__(256,2) void kv_kernel(
    const __half* __restrict__ K, const __half* __restrict__ V, float* __restrict__ P)
{
    extern __shared__ float sm[];
    const unsigned sbase = (unsigned)__cvta_generic_to_shared(sm);
    const int tid = threadIdx.x, w = tid >> 5, lane = tid & 31;
    const int g = lane >> 2, lr = lane & 3;
    const int wm = w & 3, wn = w >> 2;
    const int c0 = (blockIdx.x & 1) * 128;
    const int d0 = (blockIdx.x >> 1) * 128;
    const int chunk = blockIdx.y;
    const int b = blockIdx.z;
    const __half* Kb = K + (long)b*BCN;
    const __half* Vb = V + (long)b*BCN;
    const long nbase = (long)chunk * 1024;

    const unsigned kaoff0 = (unsigned)((wm*32 + (lane & 15))*KVPITCH)*4u + (unsigned)(lane >> 4)*16u;
    const unsigned kaoff1 = kaoff0 + (unsigned)(16*KVPITCH)*4u;
    const unsigned kboff  = (unsigned)((wn*64 + ((lane >> 4) & 1)*8 + (lane & 7))*KVPITCH)*4u
                          + (unsigned)((lane >> 3) & 1)*16u;

    auto loadChunk = [&](long nb, int buf){
        const unsigned abase = sbase + (unsigned)buf*(KVBUF*4);
        const unsigned bbase = sbase + (unsigned)(3*KVBUF*4) + (unsigned)buf*(KVBUF*4);
        #pragma unroll
        for (int i = 0; i < 2; ++i){
            int idx = tid + i*256;
            int r = idx >> 2, c8 = idx & 3;
            cpa16s(abase + (unsigned)(r*80 + c8*16), Kb + (long)(c0+r)*NN + nb + c8*8);
            cpa16s(bbase + (unsigned)(r*80 + c8*16), Vb + (long)(d0+r)*NN + nb + c8*8);
        }
        cpacommit();
    };

    loadChunk(nbase, 0);
    loadChunk(nbase + 32, 1);

    float acc[2][8][4];
    #pragma unroll
    for (int mt = 0; mt < 2; ++mt)
        #pragma unroll
        for (int nt = 0; nt < 8; ++nt)
            #pragma unroll
            for (int i = 0; i < 4; ++i) acc[mt][nt][i] = 0.f;

    int buf = 0;
    #pragma unroll 1
    for (int it = 0; it < 32; ++it){
        if (it < 31) cpawait1(); else cpawait0();
        __syncthreads();
        if (it < 30){
            int nb = buf + 2; if (nb >= 3) nb -= 3;
            loadChunk(nbase + (long)(it+2)*32, nb);
        }
        const unsigned abuf = sbase + (unsigned)buf*(KVBUF*4);
        const unsigned bbuf = sbase + (unsigned)(3*KVBUF*4) + (unsigned)buf*(KVBUF*4);
        #pragma unroll
        for (int s = 0; s < 2; ++s){
            const unsigned sb = (unsigned)s*32u;
            unsigned a0[4], a1[4];
            ldsm4(a0, abuf + kaoff0 + sb);
            ldsm4(a1, abuf + kaoff1 + sb);
            #pragma unroll
            for (int ntp = 0; ntp < 4; ++ntp){
                unsigned bb[4];
                ldsm4(bb, bbuf + kboff + (unsigned)(ntp*16*KVPITCH)*4u + sb);
                mma16(acc[0][2*ntp  ], a0, bb[0], bb[1]);
                mma16(acc[1][2*ntp  ], a1, bb[0], bb[1]);
                mma16(acc[0][2*ntp+1], a0, bb[2], bb[3]);
                mma16(acc[1][2*ntp+1], a1, bb[2], bb[3]);
            }
        }
        if (++buf == 3) buf = 0;
    }

    float* Pb = P + (long)(b*16 + chunk)*CC*CC;
    #pragma unroll
    for (int mt = 0; mt < 2; ++mt){
        #pragma unroll
        for (int half = 0; half < 2; ++half){
            const int r = c0 + wm*32 + mt*16 + g + half*8;
            #pragma unroll
            for (int nt = 0; nt < 8; ++nt){
                const int d = d0 + wn*64 + nt*8 + lr*2;
                float2 o;
                o.x = acc[mt][nt][half*2+0];
                o.y = acc[mt][nt][half*2+1];
                *(float2*)(Pb + (long)r*CC + d) = o;
            }
        }
    }
}

__global__ __launch_bounds__(256) void kvred_kernel(
    const float* __restrict__ P, __half* __restrict__ kvT)
{
    const int o = blockIdx.x * 256 + threadIdx.x;
    const int b = o >> 16;
    const int c = (o >> 8) & 255;
    const int d = o & 255;
    float s = 0.f;
    #pragma unroll
    for (int ch = 0; ch < 16; ++ch)
        s += P[((long)(b*16 + ch)*256 + c)*256 + d];
    kvT[((long)b*256 + d)*256 + c] = __float2half_rn(s * (1.0f/16.0f));
}

static const size_t HG_SMEM = (size_t)(3*WBUF + 3*BBUF + 320) * sizeof(float); // 45824
static const size_t KV_SMEM = (size_t)(6*KVBUF) * sizeof(float);               // 61440

extern "C" void kernel_launch(void* const* d_in, const int* in_sizes, int n_in,
                              void* d_out, int out_size)
{
    (void)in_sizes; (void)n_in; (void)out_size;
    const float* x   = (const float*)d_in[0];
    const float* Wq1 = (const float*)d_in[1];  const float* bq1 = (const float*)d_in[2];
    const float* Wq2 = (const float*)d_in[3];  const float* bq2 = (const float*)d_in[4];
    const float* Wk1 = (const float*)d_in[5];  const float* bk1 = (const float*)d_in[6];
    const float* Wk2 = (const float*)d_in[7];  const float* bk2 = (const float*)d_in[8];
    const float* Wv  = (const float*)d_in[9];  const float* bv  = (const float*)d_in[10];
    const float* Wg  = (const float*)d_in[11]; const float* bg  = (const float*)d_in[12];
    const float* Wo  = (const float*)d_in[13]; const float* bo  = (const float*)d_in[14];
    float* out = (float*)d_out;

    __half *t, *t2, *q, *k, *v, *g, *xp, *wp16, *w16, *kvT16;
    float *kvp, *ks, *ab, *bp;
    cudaGetSymbolAddress((void**)&t,     g_t);
    cudaGetSymbolAddress((void**)&t2,    g_t2);
    cudaGetSymbolAddress((void**)&q,     g_q);
    cudaGetSymbolAddress((void**)&k,     g_k);
    cudaGetSymbolAddress((void**)&v,     g_v);
    cudaGetSymbolAddress((void**)&g,     g_g);
    cudaGetSymbolAddress((void**)&xp,    g_xp);
    cudaGetSymbolAddress((void**)&wp16,  g_wp16);
    cudaGetSymbolAddress((void**)&w16,   g_w16);
    cudaGetSymbolAddress((void**)&kvT16, g_kvT16);
    cudaGetSymbolAddress((void**)&kvp,   g_kvp);
    cudaGetSymbolAddress((void**)&ks,    g_ks);
    cudaGetSymbolAddress((void**)&ab,    g_ab);
    cudaGetSymbolAddress((void**)&bp,    g_bp);

    cudaFuncSetAttribute((const void*)hgemm_kernel<EGELU,0,0>,
                         cudaFuncAttributeMaxDynamicSharedMemorySize, (int)HG_SMEM);
    cudaFuncSetAttribute((const void*)hgemm_kernel<ESOFT,0,0>,
                         cudaFuncAttributeMaxDynamicSharedMemorySize, (int)HG_SMEM);
    cudaFuncSetAttribute((const void*)hgemm_kernel<EATTN,1,0>,
                         cudaFuncAttributeMaxDynamicSharedMemorySize, (int)HG_SMEM);
    cudaFuncSetAttribute((const void*)hgemm_kernel<EIDENT,0,1>,
                         cudaFuncAttributeMaxDynamicSharedMemorySize, (int)HG_SMEM);
    cudaFuncSetAttribute((const void*)kv_kernel,
                         cudaFuncAttributeMaxDynamicSharedMemorySize, (int)KV_SMEM);

    statspack_kernel<<<BB*128, 256>>>(x, ab, xp);
    {
        WT wt;
        wt.W[0]=Wq1; wt.B[0]=bq1;
        wt.W[1]=Wk1; wt.B[1]=bk1;
        wt.W[2]=Wv;  wt.B[2]=bv;
        wt.W[3]=Wg;  wt.B[3]=bg;
        dim3 grid(4, BB, 4);
        wtrans_kernel<<<grid, 256>>>(wt, ab, wp16, bp);
    }
    {
        dim3 grid(64, 3);
        cvtw_kernel<<<grid, 256>>>(Wq2, Wk2, Wo, w16);
    }

    {   // stage-1 (gelu): q1->t(pair), k1->t2(pair), v(plain), g(plain)
        TP p = {};
        p.W[0]=wp16 + 0L*BB*CC*CC; p.B[0]=bp + 0*BB*CC; p.X[0]=xp; p.Y[0]=t;
        p.W[1]=wp16 + 1L*BB*CC*CC; p.B[1]=bp + 1*BB*CC; p.X[1]=xp; p.Y[1]=t2;
        p.W[2]=wp16 + 2L*BB*CC*CC; p.B[2]=bp + 2*BB*CC; p.X[2]=xp; p.Y[2]=v;
        p.W[3]=wp16 + 3L*BB*CC*CC; p.B[3]=bp + 3*BB*CC; p.X[3]=xp; p.Y[3]=g;
        p.wBatched = 1; p.bBatched = 1; p.pairMask = 0b0011;
        dim3 grid(NN/64, 8, BB);
        hgemm_kernel<EGELU,0,0><<<grid, 256, HG_SMEM>>>(p);
    }
    {   // stage-2 (softplus): q2: t->q(pair), k2: t2->k(plain)
        TP p = {};
        p.W[0]=w16 + 0L*CC*CC; p.B[0]=bq2; p.X[0]=t;  p.Y[0]=q;
        p.W[1]=w16 + 1L*CC*CC; p.B[1]=bk2; p.X[1]=t2; p.Y[1]=k;
        p.wBatched = 0; p.bBatched = 0; p.pairMask = 0b01;
        dim3 grid(NN/64, 4, BB);
        hgemm_kernel<ESOFT,0,0><<<grid, 256, HG_SMEM>>>(p);
    }
    ksum_kernel<<<BB*CC, 256>>>(k, ks);
    {
        dim3 grid(4, 16, BB);
        kv_kernel<<<grid, 256, KV_SMEM>>>(k, v, kvp);
    }
    kvred_kernel<<<BB*CC, 256>>>(kvp, kvT16);
    {   // attn: t = (kvT.q + v) * z * g   (paired out)
        TP p = {};
        p.W[0]=kvT16; p.B[0]=nullptr; p.X[0]=q; p.Y[0]=t;
        p.Vp = v; p.Gp = g; p.ksp = ks;
        p.wBatched = 1; p.bBatched = 0; p.pairMask = 0b1;
        dim3 grid(NN/64, 2, BB);
        hgemm_kernel<EATTN,1,0><<<grid, 256, HG_SMEM>>>(p);
    }
    {   // final: out = Wo.t + bo (f32 out)
        TP p = {};
        p.W[0]=w16 + 2L*CC*CC; p.B[0]=bo; p.X[0]=t; p.Yf = out;
        p.wBatched = 0; p.bBatched = 0; p.pairMask = 0;
        dim3 grid(NN/64, 2, BB);
        hgemm_kernel<EIDENT,0,1><<<grid, 256, HG_SMEM>>>(p);
    }
}

// round 15
// speedup vs baseline: 1.1919x; 1.0481x over previous
#include <cuda_runtime.h>
#include <cuda_fp16.h>
#include <math.h>
#include <stdint.h>

#define CC 256
#define NN 16384
#define BB 4
#define BCN (CC*NN)
#define EGELU 0
#define ESOFT 1
#define EIDENT 2
#define EATTN 3
#define WPITCH 20
#define WBUF (128*WPITCH)          // 2560 words per buffer (128 rows)
#define BPITCH 72
#define BBUF (16*BPITCH)           // 1152 words per buffer
#define KVPITCH 20
#define KVBUF (128*KVPITCH)

__device__ __half g_t  [BB*BCN];   // paired [c2][n]
__device__ __half g_t2 [BB*BCN];   // paired
__device__ __half g_q  [BB*BCN];   // paired
__device__ __half g_k  [BB*BCN];   // plain [c][n]
__device__ __half g_v  [BB*BCN];   // plain
__device__ __half g_g  [BB*BCN];   // plain
__device__ __half g_xp [BB*BCN];   // paired
__device__ __half g_wp16[4*BB*CC*CC];
__device__ __half g_w16 [3*CC*CC];
__device__ __half g_kvT16[BB*CC*CC];
__device__ float  g_kvp[BB*16*CC*CC];
__device__ float  g_ks [BB*CC];
__device__ float  g_ab [2*BB*CC];
__device__ float  g_bp [4*BB*CC];

__device__ __forceinline__ void cpa16s(unsigned s, const void* g){
    asm volatile("cp.async.cg.shared.global [%0], [%1], 16;\n" :: "r"(s), "l"(g));
}
__device__ __forceinline__ void cpacommit(){ asm volatile("cp.async.commit_group;\n"); }
__device__ __forceinline__ void cpawait0(){ asm volatile("cp.async.wait_group 0;\n"); }
__device__ __forceinline__ void cpawait1(){ asm volatile("cp.async.wait_group 1;\n"); }
__device__ __forceinline__ void mma16(float* d, const unsigned* a, unsigned b0, unsigned b1){
    asm volatile(
      "mma.sync.aligned.m16n8k16.row.col.f32.f16.f16.f32 "
      "{%0,%1,%2,%3},{%4,%5,%6,%7},{%8,%9},{%0,%1,%2,%3};\n"
      : "+f"(d[0]), "+f"(d[1]), "+f"(d[2]), "+f"(d[3])
      : "r"(a[0]), "r"(a[1]), "r"(a[2]), "r"(a[3]), "r"(b0), "r"(b1));
}
__device__ __forceinline__ void ldsm4(unsigned* r, unsigned addr){
    asm volatile("ldmatrix.sync.aligned.m8n8.x4.shared.b16 {%0,%1,%2,%3}, [%4];"
        : "=r"(r[0]), "=r"(r[1]), "=r"(r[2]), "=r"(r[3]) : "r"(addr));
}
__device__ __forceinline__ unsigned packh(float lo, float hi){
    unsigned r;
    asm("cvt.rn.f16x2.f32 %0, %1, %2;" : "=r"(r) : "f"(hi), "f"(lo));
    return r;
}
__device__ __forceinline__ float2 h2f(unsigned u){
    __half2 h = *(__half2*)&u;
    return __half22float2(h);
}
__device__ __forceinline__ float geluf(float x){
    return 0.5f * x * (1.0f + erff(x * 0.70710678118654752440f));
}
__device__ __forceinline__ float softplusf(float x){
    return fmaxf(x, 0.0f) + log1pf(expf(-fabsf(x)));
}
__device__ __forceinline__ float epi_apply(int EPI, float x){
    if (EPI == EGELU) return geluf(x);
    if (EPI == ESOFT) return softplusf(x);
    return x;
}

// ---- merged norm-stats + fp16 pair-pack of x ---------------------------------
__global__ __launch_bounds__(256) void statspack_kernel(
    const float* __restrict__ x, float* __restrict__ ab, __half* __restrict__ xp)
{
    const int b = blockIdx.x >> 7, c2 = blockIdx.x & 127;
    const int tid = threadIdx.x;
    const float* r0 = x + ((long)b*CC + 2*c2)*NN;
    const float* r1 = r0 + NN;
    __half2* xo = (__half2*)xp + (long)(b*128 + c2)*NN;
    float s0=0.f, q0=0.f, s1=0.f, q1=0.f;
    #pragma unroll
    for (int i = 0; i < 16; ++i){
        int idx = (tid + i*256)*4;
        float4 a = *(const float4*)(r0 + idx);
        float4 c = *(const float4*)(r1 + idx);
        s0 += a.x+a.y+a.z+a.w;
        q0 += a.x*a.x + a.y*a.y + a.z*a.z + a.w*a.w;
        s1 += c.x+c.y+c.z+c.w;
        q1 += c.x*c.x + c.y*c.y + c.z*c.z + c.w*c.w;
        *(uint4*)(xo + idx) = make_uint4(packh(a.x,c.x), packh(a.y,c.y),
                                         packh(a.z,c.z), packh(a.w,c.w));
    }
    #pragma unroll
    for (int o = 16; o; o >>= 1){
        s0 += __shfl_xor_sync(0xffffffffu, s0, o);
        q0 += __shfl_xor_sync(0xffffffffu, q0, o);
        s1 += __shfl_xor_sync(0xffffffffu, s1, o);
        q1 += __shfl_xor_sync(0xffffffffu, q1, o);
    }
    __shared__ float sh[32];
    const int w = tid >> 5, lane = tid & 31;
    if (lane == 0){ sh[w] = s0; sh[8+w] = q0; sh[16+w] = s1; sh[24+w] = q1; }
    __syncthreads();
    if (tid < 2){
        float ts = 0.f, tq = 0.f;
        #pragma unroll
        for (int i = 0; i < 8; ++i){ ts += sh[tid*16 + i]; tq += sh[tid*16 + 8 + i]; }
        float mu  = ts * (1.0f/NN);
        float var = tq * (1.0f/NN) - mu*mu;
        float rs  = rsqrtf(var + 1e-5f);
        int c = 2*c2 + tid;
        ab[b*CC + c] = rs;
        ab[BB*CC + b*CC + c] = -mu*rs;
    }
}

struct WT { const float* W[4]; const float* B[4]; };
__global__ __launch_bounds__(256) void wtrans_kernel(
    WT p, const float* __restrict__ ab,
    __half* __restrict__ wp, float* __restrict__ bp)
{
    __shared__ float AL[256], BE[256];
    const int y = blockIdx.x, b = blockIdx.y, rg = blockIdx.z;
    const int tid = threadIdx.x, w = tid >> 5, lane = tid & 31;
    AL[tid] = ab[b*CC + tid];
    BE[tid] = ab[BB*CC + b*CC + tid];
    __syncthreads();
    const float* W = p.W[y];
    __half* wpo = wp + (long)(y*BB + b)*CC*CC;
    const int k0 = lane*8;
    #pragma unroll 1
    for (int pass = 0; pass < 8; ++pass){
        int m = rg*64 + pass*8 + w;
        const float* wr = W + (long)m*CC;
        float4 w0 = *(const float4*)(wr + k0);
        float4 w1 = *(const float4*)(wr + k0 + 4);
        float bacc = w0.x*BE[k0] + w0.y*BE[k0+1] + w0.z*BE[k0+2] + w0.w*BE[k0+3]
                   + w1.x*BE[k0+4] + w1.y*BE[k0+5] + w1.z*BE[k0+6] + w1.w*BE[k0+7];
        unsigned h0 = packh(w0.x*AL[k0],   w0.y*AL[k0+1]);
        unsigned h1 = packh(w0.z*AL[k0+2], w0.w*AL[k0+3]);
        unsigned h2 = packh(w1.x*AL[k0+4], w1.y*AL[k0+5]);
        unsigned h3 = packh(w1.z*AL[k0+6], w1.w*AL[k0+7]);
        *(uint4*)(wpo + (long)m*CC + k0) = make_uint4(h0,h1,h2,h3);
        #pragma unroll
        for (int o = 16; o; o >>= 1) bacc += __shfl_xor_sync(0xffffffffu, bacc, o);
        if (lane == 0) bp[(y*BB + b)*CC + m] = p.B[y][m] + bacc;
    }
}

__global__ __launch_bounds__(256) void cvtw_kernel(
    const float* __restrict__ W0, const float* __restrict__ W1,
    const float* __restrict__ W2, __half* __restrict__ outw)
{
    const float* Ws = (blockIdx.y == 0) ? W0 : (blockIdx.y == 1 ? W1 : W2);
    long i = ((long)blockIdx.x*256 + threadIdx.x)*4;
    float4 v = *(const float4*)(Ws + i);
    unsigned h0 = packh(v.x, v.y), h1 = packh(v.z, v.w);
    *(uint2*)(outw + (long)blockIdx.y*CC*CC + i) = make_uint2(h0, h1);
}

__global__ __launch_bounds__(256) void ksum_kernel(
    const __half* __restrict__ k, float* __restrict__ ks)
{
    const uint4* kp = (const uint4*)(k + (long)blockIdx.x*NN);
    const int tid = threadIdx.x;
    float s = 0.f;
    #pragma unroll
    for (int i = 0; i < 8; ++i){
        uint4 t = kp[tid + i*256];
        float2 f0 = h2f(t.x), f1 = h2f(t.y), f2 = h2f(t.z), f3 = h2f(t.w);
        s += f0.x+f0.y+f1.x+f1.y+f2.x+f2.y+f3.x+f3.y;
    }
    #pragma unroll
    for (int o = 16; o; o >>= 1) s += __shfl_xor_sync(0xffffffffu, s, o);
    __shared__ float sh[8];
    const int w = tid >> 5, lane = tid & 31;
    if (lane == 0) sh[w] = s;
    __syncthreads();
    if (tid == 0){
        float ts = 0.f;
        #pragma unroll
        for (int i = 0; i < 8; ++i) ts += sh[i];
        ks[blockIdx.x] = ts * (1.0f/16.0f);
    }
}

// ---- GEMM: M-tile 128, N-tile 64; 8 warps = 4 rowgrp x 2 colhalf; 3-stage pipe
struct TP {
    const __half* W[4]; const float* B[4];
    const __half* X[4];
    __half* Y[4];
    float* Yf;
    const __half* Vp; const __half* Gp; const float* ksp;
    int wBatched, bBatched, pairMask;
};

template<int EPI, int ZFUSE, int OUTF32>
__global__ __launch_bounds__(256,4) void hgemm_kernel(TP p)
{
    extern __shared__ float sm[];
    float* KSs = sm + 3*WBUF + 3*BBUF;
    float* ZSs = KSs + 256;
    const unsigned sbase = (unsigned)__cvta_generic_to_shared(sm);

    const int tid = threadIdx.x, w = tid >> 5, lane = tid & 31;
    const int g = lane >> 2, lr = lane & 3;
    const int wm = w & 3, wn = w >> 2;
    const int y = blockIdx.y >> 1;
    const int m0 = (blockIdx.y & 1) * 128;
    const int b = blockIdx.z;
    const long n0 = (long)blockIdx.x * 64;
    const __half* W1 = p.W[y] + (p.wBatched ? (long)b*CC*CC : 0) + (long)m0*CC;
    const __half2* X2 = (const __half2*)p.X[y] + (long)b*(BCN/2);

    if (ZFUSE) KSs[tid] = p.ksp[b*CC + tid];

    const unsigned aoff0 = (unsigned)((wm*32 + (lane & 15))*WPITCH)*4u + (unsigned)(lane >> 4)*16u;
    const unsigned aoff1 = aoff0 + (unsigned)(16*WPITCH)*4u;

    auto loadChunk = [&](int kc, int buf){
        const unsigned wbase = sbase + (unsigned)buf*(WBUF*4);
        const unsigned bbase = sbase + (unsigned)(3*WBUF*4) + (unsigned)buf*(BBUF*4);
        #pragma unroll
        for (int i = 0; i < 2; ++i){
            int idx = tid + i*256;
            int r = idx >> 2, c = idx & 3;
            cpa16s(wbase + (unsigned)(r*80 + c*16), W1 + (long)r*CC + kc*32 + c*8);
        }
        {
            int r = tid >> 4, c = tid & 15;
            cpa16s(bbase + (unsigned)(r*288 + c*16), X2 + (long)(kc*16 + r)*NN + n0 + c*4);
        }
        cpacommit();
    };

    loadChunk(0, 0);
    loadChunk(1, 1);

    float acc[2][4][4];
    #pragma unroll
    for (int mt = 0; mt < 2; ++mt)
        #pragma unroll
        for (int nt = 0; nt < 4; ++nt)
            #pragma unroll
            for (int i = 0; i < 4; ++i) acc[mt][nt][i] = 0.f;
    float zreg = 0.f;

    int buf = 0;
    #pragma unroll 1
    for (int kc = 0; kc < 8; ++kc){
        if (kc < 7) cpawait1(); else cpawait0();
        __syncthreads();
        if (kc < 6){
            int nb = buf + 2; if (nb >= 3) nb -= 3;
            loadChunk(kc+2, nb);
        }
        const unsigned wbuf = sbase + (unsigned)buf*(WBUF*4);
        const unsigned* Bu = (const unsigned*)(sm + 3*WBUF + buf*BBUF);
        if (ZFUSE && tid < 64){
            #pragma unroll
            for (int kk = 0; kk < 16; ++kk){
                float2 f = h2f(Bu[kk*BPITCH + tid]);
                zreg = fmaf(f.x, KSs[kc*32 + 2*kk],     zreg);
                zreg = fmaf(f.y, KSs[kc*32 + 2*kk + 1], zreg);
            }
        }
        #pragma unroll
        for (int s = 0; s < 2; ++s){
            const int s8 = s*8;
            unsigned a0[4], a1[4];
            ldsm4(a0, wbuf + aoff0 + (unsigned)s8*4u);
            ldsm4(a1, wbuf + aoff1 + (unsigned)s8*4u);
            #pragma unroll
            for (int nt = 0; nt < 4; ++nt){
                unsigned b0 = Bu[(s8 + lr    )*BPITCH + wn*32 + nt*8 + g];
                unsigned b1 = Bu[(s8 + lr + 4)*BPITCH + wn*32 + nt*8 + g];
                mma16(acc[0][nt], a0, b0, b1);
                mma16(acc[1][nt], a1, b0, b1);
            }
        }
        if (++buf == 3) buf = 0;
    }

    if (ZFUSE){
        __syncthreads();
        if (tid < 64) ZSs[tid] = 1.0f / (zreg + (float)NN);
        __syncthreads();
    }

    const int pair = (p.pairMask >> y) & 1;

    #pragma unroll
    for (int mt = 0; mt < 2; ++mt){
        const int r0 = m0 + wm*32 + mt*16 + g;
        const int r1 = r0 + 8;
        float bi0 = 0.f, bi1 = 0.f;
        if (EPI != EATTN){
            const float* bb = p.B[y] + (p.bBatched ? b*CC : 0);
            bi0 = bb[r0]; bi1 = bb[r1];
        }
        #pragma unroll
        for (int nt = 0; nt < 4; ++nt){
            const int col = wn*32 + nt*8 + 2*lr;
            float x00 = acc[mt][nt][0] + bi0;
            float x01 = acc[mt][nt][1] + bi0;
            float x10 = acc[mt][nt][2] + bi1;
            float x11 = acc[mt][nt][3] + bi1;
            if (EPI == EATTN){
                const __half* Vb = p.Vp + (long)b*BCN;
                const __half* Gb = p.Gp + (long)b*BCN;
                float2 v0 = h2f(*(const unsigned*)(Vb + (long)r0*NN + n0 + col));
                float2 v1 = h2f(*(const unsigned*)(Vb + (long)r1*NN + n0 + col));
                float2 g0 = h2f(*(const unsigned*)(Gb + (long)r0*NN + n0 + col));
                float2 g1 = h2f(*(const unsigned*)(Gb + (long)r1*NN + n0 + col));
                float z0 = ZSs[col], z1 = ZSs[col+1];
                x00 = (x00 + v0.x) * z0 * g0.x;
                x01 = (x01 + v0.y) * z1 * g0.y;
                x10 = (x10 + v1.x) * z0 * g1.x;
                x11 = (x11 + v1.y) * z1 * g1.y;
            } else {
                x00 = epi_apply(EPI, x00); x01 = epi_apply(EPI, x01);
                x10 = epi_apply(EPI, x10); x11 = epi_apply(EPI, x11);
            }
            if (OUTF32){
                float* Yf = p.Yf + (long)b*BCN;
                *(float2*)(Yf + (long)r0*NN + n0 + col) = make_float2(x00, x01);
                *(float2*)(Yf + (long)r1*NN + n0 + col) = make_float2(x10, x11);
            } else if (pair){
                float u00 = __shfl_down_sync(0xffffffffu, x00, 4);
                float u01 = __shfl_down_sync(0xffffffffu, x01, 4);
                float u10 = __shfl_down_sync(0xffffffffu, x10, 4);
                float u11 = __shfl_down_sync(0xffffffffu, x11, 4);
                if (!(g & 1)){
                    __half2* Y2 = (__half2*)p.Y[y] + (long)b*(BCN/2);
                    *(uint2*)(Y2 + (long)(r0>>1)*NN + n0 + col) =
                        make_uint2(packh(x00, u00), packh(x01, u01));
                    *(uint2*)(Y2 + (long)(r1>>1)*NN + n0 + col) =
                        make_uint2(packh(x10, u10), packh(x11, u11));
                }
            } else {
                __half* Yh = p.Y[y] + (long)b*BCN;
                *(unsigned*)(Yh + (long)r0*NN + n0 + col) = packh(x00, x01);
                *(unsigned*)(Yh + (long)r1*NN + n0 + col) = packh(x10, x11);
            }
        }
    }
}

// ---- kv partial GEMM: 3-stage pipeline, single barrier per chunk -------------
__global__ __launch_bounds__(256,2) void kv_kernel(
    const __half* __restrict__ K, const __half* __restrict__ V, float* __restrict__ P)
{
    extern __shared__ float sm[];
    const unsigned sbase = (unsigned)__cvta_generic_to_shared(sm);
    const int tid = threadIdx.x, w = tid >> 5, lane = tid & 31;
    const int g = lane >> 2, lr = lane & 3;
    const int wm = w & 3, wn = w >> 2;
    const int c0 = (blockIdx.x & 1) * 128;
    const int d0 = (blockIdx.x >> 1) * 128;
    const int chunk = blockIdx.y;
    const int b = blockIdx.z;
    const __half* Kb = K + (long)b*BCN;
    const __half* Vb = V + (long)b*BCN;
    const long nbase = (long)chunk * 1024;

    const unsigned kaoff0 = (unsigned)((wm*32 + (lane & 15))*KVPITCH)*4u + (unsigned)(lane >> 4)*16u;
    const unsigned kaoff1 = kaoff0 + (unsigned)(16*KVPITCH)*4u;
    const unsigned kboff  = (unsigned)((wn*64 + ((lane >> 4) & 1)*8 + (lane & 7))*KVPITCH)*4u
                          + (unsigned)((lane >> 3) & 1)*16u;

    auto loadChunk = [&](long nb, int buf){
        const unsigned abase = sbase + (unsigned)buf*(KVBUF*4);
        const unsigned bbase = sbase + (unsigned)(3*KVBUF*4) + (unsigned)buf*(KVBUF*4);
        #pragma unroll
        for (int i = 0; i < 2; ++i){
            int idx = tid + i*256;
            int r = idx >> 2, c8 = idx & 3;
            cpa16s(abase + (unsigned)(r*80 + c8*16), Kb + (long)(c0+r)*NN + nb + c8*8);
            cpa16s(bbase + (unsigned)(r*80 + c8*16), Vb + (long)(d0+r)*NN + nb + c8*8);
        }
        cpacommit();
    };

    loadChunk(nbase, 0);
    loadChunk(nbase + 32, 1);

    float acc[2][8][4];
    #pragma unroll
    for (int mt = 0; mt < 2; ++mt)
        #pragma unroll
        for (int nt = 0; nt < 8; ++nt)
            #pragma unroll
            for (int i = 0; i < 4; ++i) acc[mt][nt][i] = 0.f;

    int buf = 0;
    #pragma unroll 1
    for (int it = 0; it < 32; ++it){
        if (it < 31) cpawait1(); else cpawait0();
        __syncthreads();
        if (it < 30){
            int nb = buf + 2; if (nb >= 3) nb -= 3;
            loadChunk(nbase + (long)(it+2)*32, nb);
        }
        const unsigned abuf = sbase + (unsigned)buf*(KVBUF*4);
        const unsigned bbuf = sbase + (unsigned)(3*KVBUF*4) + (unsigned)buf*(KVBUF*4);
        #pragma unroll
        for (int s = 0; s < 2; ++s){
            const unsigned sb = (unsigned)s*32u;
            unsigned a0[4], a1[4];
            ldsm4(a0, abuf + kaoff0 + sb);
            ldsm4(a1, abuf + kaoff1 + sb);
            #pragma unroll
            for (int ntp = 0; ntp < 4; ++ntp){
                unsigned bb[4];
                ldsm4(bb, bbuf + kboff + (unsigned)(ntp*16*KVPITCH)*4u + sb);
                mma16(acc[0][2*ntp  ], a0, bb[0], bb[1]);
                mma16(acc[1][2*ntp  ], a1, bb[0], bb[1]);
                mma16(acc[0][2*ntp+1], a0, bb[2], bb[3]);
                mma16(acc[1][2*ntp+1], a1, bb[2], bb[3]);
            }
        }
        if (++buf == 3) buf = 0;
    }

    float* Pb = P + (long)(b*16 + chunk)*CC*CC;
    #pragma unroll
    for (int mt = 0; mt < 2; ++mt){
        #pragma unroll
        for (int half = 0; half < 2; ++half){
            const int r = c0 + wm*32 + mt*16 + g + half*8;
            #pragma unroll
            for (int nt = 0; nt < 8; ++nt){
                const int d = d0 + wn*64 + nt*8 + lr*2;
                float2 o;
                o.x = acc[mt][nt][half*2+0];
                o.y = acc[mt][nt][half*2+1];
                *(float2*)(Pb + (long)r*CC + d) = o;
            }
        }
    }
}

__global__ __launch_bounds__(256) void kvred_kernel(
    const float* __restrict__ P, __half* __restrict__ kvT)
{
    const int o = blockIdx.x * 256 + threadIdx.x;
    const int b = o >> 16;
    const int c = (o >> 8) & 255;
    const int d = o & 255;
    float s = 0.f;
    #pragma unroll
    for (int ch = 0; ch < 16; ++ch)
        s += P[((long)(b*16 + ch)*256 + c)*256 + d];
    kvT[((long)b*256 + d)*256 + c] = __float2half_rn(s * (1.0f/16.0f));
}

static const size_t HG_SMEM = (size_t)(3*WBUF + 3*BBUF + 320) * sizeof(float); // 45824
static const size_t KV_SMEM = (size_t)(6*KVBUF) * sizeof(float);               // 61440

extern "C" void kernel_launch(void* const* d_in, const int* in_sizes, int n_in,
                              void* d_out, int out_size)
{
    (void)in_sizes; (void)n_in; (void)out_size;
    const float* x   = (const float*)d_in[0];
    const float* Wq1 = (const float*)d_in[1];  const float* bq1 = (const float*)d_in[2];
    const float* Wq2 = (const float*)d_in[3];  const float* bq2 = (const float*)d_in[4];
    const float* Wk1 = (const float*)d_in[5];  const float* bk1 = (const float*)d_in[6];
    const float* Wk2 = (const float*)d_in[7];  const float* bk2 = (const float*)d_in[8];
    const float* Wv  = (const float*)d_in[9];  const float* bv  = (const float*)d_in[10];
    const float* Wg  = (const float*)d_in[11]; const float* bg  = (const float*)d_in[12];
    const float* Wo  = (const float*)d_in[13]; const float* bo  = (const float*)d_in[14];
    float* out = (float*)d_out;

    __half *t, *t2, *q, *k, *v, *g, *xp, *wp16, *w16, *kvT16;
    float *kvp, *ks, *ab, *bp;
    cudaGetSymbolAddress((void**)&t,     g_t);
    cudaGetSymbolAddress((void**)&t2,    g_t2);
    cudaGetSymbolAddress((void**)&q,     g_q);
    cudaGetSymbolAddress((void**)&k,     g_k);
    cudaGetSymbolAddress((void**)&v,     g_v);
    cudaGetSymbolAddress((void**)&g,     g_g);
    cudaGetSymbolAddress((void**)&xp,    g_xp);
    cudaGetSymbolAddress((void**)&wp16,  g_wp16);
    cudaGetSymbolAddress((void**)&w16,   g_w16);
    cudaGetSymbolAddress((void**)&kvT16, g_kvT16);
    cudaGetSymbolAddress((void**)&kvp,   g_kvp);
    cudaGetSymbolAddress((void**)&ks,    g_ks);
    cudaGetSymbolAddress((void**)&ab,    g_ab);
    cudaGetSymbolAddress((void**)&bp,    g_bp);

    cudaFuncSetAttribute((const void*)hgemm_kernel<EGELU,0,0>,
                         cudaFuncAttributeMaxDynamicSharedMemorySize, (int)HG_SMEM);
    cudaFuncSetAttribute((const void*)hgemm_kernel<ESOFT,0,0>,
                         cudaFuncAttributeMaxDynamicSharedMemorySize, (int)HG_SMEM);
    cudaFuncSetAttribute((const void*)hgemm_kernel<EATTN,1,0>,
                         cudaFuncAttributeMaxDynamicSharedMemorySize, (int)HG_SMEM);
    cudaFuncSetAttribute((const void*)hgemm_kernel<EIDENT,0,1>,
                         cudaFuncAttributeMaxDynamicSharedMemorySize, (int)HG_SMEM);
    cudaFuncSetAttribute((const void*)kv_kernel,
                         cudaFuncAttributeMaxDynamicSharedMemorySize, (int)KV_SMEM);

    statspack_kernel<<<BB*128, 256>>>(x, ab, xp);
    {
        WT wt;
        wt.W[0]=Wq1; wt.B[0]=bq1;
        wt.W[1]=Wk1; wt.B[1]=bk1;
        wt.W[2]=Wv;  wt.B[2]=bv;
        wt.W[3]=Wg;  wt.B[3]=bg;
        dim3 grid(4, BB, 4);
        wtrans_kernel<<<grid, 256>>>(wt, ab, wp16, bp);
    }
    {
        dim3 grid(64, 3);
        cvtw_kernel<<<grid, 256>>>(Wq2, Wk2, Wo, w16);
    }

    {   // stage-1 (gelu): q1->t(pair), k1->t2(pair), v(plain), g(plain)
        TP p = {};
        p.W[0]=wp16 + 0L*BB*CC*CC; p.B[0]=bp + 0*BB*CC; p.X[0]=xp; p.Y[0]=t;
        p.W[1]=wp16 + 1L*BB*CC*CC; p.B[1]=bp + 1*BB*CC; p.X[1]=xp; p.Y[1]=t2;
        p.W[2]=wp16 + 2L*BB*CC*CC; p.B[2]=bp + 2*BB*CC; p.X[2]=xp; p.Y[2]=v;
        p.W[3]=wp16 + 3L*BB*CC*CC; p.B[3]=bp + 3*BB*CC; p.X[3]=xp; p.Y[3]=g;
        p.wBatched = 1; p.bBatched = 1; p.pairMask = 0b0011;
        dim3 grid(NN/64, 8, BB);
        hgemm_kernel<EGELU,0,0><<<grid, 256, HG_SMEM>>>(p);
    }
    {   // stage-2 (softplus): q2: t->q(pair), k2: t2->k(plain)
        TP p = {};
        p.W[0]=w16 + 0L*CC*CC; p.B[0]=bq2; p.X[0]=t;  p.Y[0]=q;
        p.W[1]=w16 + 1L*CC*CC; p.B[1]=bk2; p.X[1]=t2; p.Y[1]=k;
        p.wBatched = 0; p.bBatched = 0; p.pairMask = 0b01;
        dim3 grid(NN/64, 4, BB);
        hgemm_kernel<ESOFT,0,0><<<grid, 256, HG_SMEM>>>(p);
    }
    ksum_kernel<<<BB*CC, 256>>>(k, ks);
    {
        dim3 grid(4, 16, BB);
        kv_kernel<<<grid, 256, KV_SMEM>>>(k, v, kvp);
    }
    kvred_kernel<<<BB*CC, 256>>>(kvp, kvT16);
    {   // attn: t = (kvT.q + v) * z * g   (paired out)
        TP p = {};
        p.W[0]=kvT16; p.B[0]=nullptr; p.X[0]=q; p.Y[0]=t;
        p.Vp = v; p.Gp = g; p.ksp = ks;
        p.wBatched = 1; p.bBatched = 0; p.pairMask = 0b1;
        dim3 grid(NN/64, 2, BB);
        hgemm_kernel<EATTN,1,0><<<grid, 256, HG_SMEM>>>(p);
    }
    {   // final: out = Wo.t + bo (f32 out)
        TP p = {};
        p.W[0]=w16 + 2L*CC*CC; p.B[0]=bo; p.X[0]=t; p.Yf = out;
        p.wBatched = 0; p.bBatched = 0; p.pairMask = 0;
        dim3 grid(NN/64, 2, BB);
        hgemm_kernel<EIDENT,0,1><<<grid, 256, HG_SMEM>>>(p);
    }
}